// round 12
// baseline (speedup 1.0000x reference)
#include <cuda_runtime.h>
#include <cuda_bf16.h>
#include <math.h>
#include <stdint.h>

#define Nn   4096
#define Mm   2048
#define IS   128
#define XC   129
#define INDIM 257
#define QDIM 32
#define KP   288      // gate-GEMM K (257 + bias col + pad)
#define NB1  320      // gemm1 out width

typedef unsigned long long ull;
typedef __nv_bfloat16 bf16;

// Scratch
__device__ __align__(16) bf16 g_cbhi[Nn * NB1];
__device__ __align__(16) bf16 g_cblo[Nn * NB1];
__device__ __align__(16) bf16 g_ajhi[Mm * Nn];
__device__ __align__(16) bf16 g_ajlo[Mm * Nn];
__device__ float g_pg1 [4 * Mm * NB1];
__device__ __align__(16) bf16 g_cghi[Mm * KP];
__device__ __align__(16) bf16 g_cglo[Mm * KP];
__device__ __align__(16) bf16 g_cnhi[Mm * KP];
__device__ __align__(16) bf16 g_cnlo[Mm * KP];
__device__ __align__(16) bf16 g_Whi[(size_t)3 * 32 * KP * IS];
__device__ __align__(16) bf16 g_Wlo[(size_t)3 * 32 * KP * IS];
__device__ float g_pr [4 * Mm * IS];
__device__ float g_pu [4 * Mm * IS];
__device__ float g_pc [8 * Mm * IS];
__device__ float g_r  [Mm * IS];
__device__ float g_u  [Mm * IS];

__device__ __forceinline__ float sigmoidf_(float v) { return 1.0f / (1.0f + expf(-v)); }
__device__ __forceinline__ void cpa16(uint32_t dst, const void* src) {
    asm volatile("cp.async.ca.shared.global [%0], [%1], 16;" :: "r"(dst), "l"(src));
}
#define CP_COMMIT() asm volatile("cp.async.commit_group;")
#define CP_WAIT0()  asm volatile("cp.async.wait_group 0;")
#define CP_WAIT1()  asm volatile("cp.async.wait_group 1;")

#define LDSMX4(R, ADDR)                                                       \
    asm volatile("ldmatrix.sync.aligned.m8n8.x4.shared.b16 {%0,%1,%2,%3}, [%4];" \
        : "=r"((R)[0]), "=r"((R)[1]), "=r"((R)[2]), "=r"((R)[3]) : "r"(ADDR))
#define LDSMX4T(R, ADDR)                                                      \
    asm volatile("ldmatrix.sync.aligned.m8n8.x4.trans.shared.b16 {%0,%1,%2,%3}, [%4];" \
        : "=r"((R)[0]), "=r"((R)[1]), "=r"((R)[2]), "=r"((R)[3]) : "r"(ADDR))
#define MMA(C, A, B)                                                          \
    asm volatile("mma.sync.aligned.m16n8k16.row.col.f32.bf16.bf16.f32 "       \
        "{%0,%1,%2,%3}, {%4,%5,%6,%7}, {%8,%9}, {%0,%1,%2,%3};"               \
        : "+f"((C)[0]), "+f"((C)[1]), "+f"((C)[2]), "+f"((C)[3])              \
        : "r"((A)[0]), "r"((A)[1]), "r"((A)[2]), "r"((A)[3]),                 \
          "r"((B)[0]), "r"((B)[1]))

__device__ __forceinline__ void bsplit(float v, bf16& hi, bf16& lo) {
    hi = __float2bfloat16(v);
    lo = __float2bfloat16(v - __bfloat162float(hi));
}

// ---------------------------------------------------------------------------
__global__ void k_cat_split(const float* __restrict__ x, const float* __restrict__ h) {
    int idx = blockIdx.x * 256 + threadIdx.x;
    if (idx >= Nn * NB1) return;
    int row = idx / NB1, c = idx - row * NB1;
    float v = 0.0f;
    if (c < XC)        v = x[row * XC + c];
    else if (c < INDIM) v = h[row * IS + (c - XC)];
    bf16 hi, lo; bsplit(v, hi, lo);
    g_cbhi[idx] = hi; g_cblo[idx] = lo;
}

__global__ void k_adj_split(const float* __restrict__ adj, const int* __restrict__ nodes) {
    int i4 = blockIdx.x * 256 + threadIdx.x;
    if (i4 >= Mm * Nn / 4) return;
    int m = i4 >> 10;
    int k4 = (i4 & 1023) * 4;
    float4 v = *(const float4*)&adj[(size_t)nodes[m] * Nn + k4];
    bf16 h[4], l[4];
    bsplit(v.x, h[0], l[0]); bsplit(v.y, h[1], l[1]);
    bsplit(v.z, h[2], l[2]); bsplit(v.w, h[3], l[3]);
    *(ull*)&g_ajhi[(size_t)m * Nn + k4] = *(ull*)h;
    *(ull*)&g_ajlo[(size_t)m * Nn + k4] = *(ull*)l;
}

// ---------------------------------------------------------------------------
// Tensor GEMM1: BM=128, BN=64, K-split 4. grid (5, 16, 4), 2 CTA/SM.
// 3-stage cp.async pipeline: A buf 20480B x3 at 0, B buf 9216B x3 at 61440.
// dyn smem 89088.
// ---------------------------------------------------------------------------
__global__ __launch_bounds__(256, 2) void k_mma_g1() {
    extern __shared__ char sm[];
    uint32_t su = (uint32_t)__cvta_generic_to_shared(sm);
    int t = threadIdx.x, lane = t & 31, wid = t >> 5;
    int n0 = blockIdx.x * 64, m0 = blockIdx.y * 128, ks = blockIdx.z * 1024;
    int mw = wid >> 1, nw = wid & 1;
    uint32_t aB = su + (uint32_t)((mw * 32 + (lane & 15)) * 80 + (lane >> 4) * 16);
    uint32_t bB = su + 61440u + (uint32_t)((lane & 15) * 144 + (nw * 32 + (lane >> 4) * 8) * 2);

    float acc[2][4][4];
#pragma unroll
    for (int mi = 0; mi < 2; mi++)
#pragma unroll
        for (int ni = 0; ni < 4; ni++)
#pragma unroll
            for (int j = 0; j < 4; j++) acc[mi][ni][j] = 0.0f;

#define G1LD(KC, NB)                                                          \
    {                                                                         \
        int _k0 = ks + (KC) * 32;                                             \
        _Pragma("unroll")                                                     \
        for (int pr = 0; pr < 2; pr++) {                                      \
            const bf16* sa = pr ? g_ajlo : g_ajhi;                            \
            _Pragma("unroll")                                                 \
            for (int p = 0; p < 2; p++) {                                     \
                int e = t + 256 * p;                                          \
                int row = e >> 2, gg = e & 3;                                 \
                cpa16(su + (uint32_t)((NB) * 20480 + pr * 10240 + row * 80 + gg * 16), \
                      sa + (size_t)(m0 + row) * Nn + _k0 + gg * 8);           \
            }                                                                 \
            const bf16* sb = pr ? g_cblo : g_cbhi;                            \
            int k = t >> 3, gg2 = t & 7;                                      \
            cpa16(su + (uint32_t)(61440 + (NB) * 9216 + pr * 4608 + k * 144 + gg2 * 16), \
                  sb + (size_t)(_k0 + k) * NB1 + n0 + gg2 * 8);               \
        }                                                                     \
    }

    G1LD(0, 0);
    CP_COMMIT();
    G1LD(1, 1);
    CP_COMMIT();
    CP_WAIT1();
    __syncthreads();

    const int NIT = 32;
    for (int it = 0; it < NIT; it++) {
        int buf = it % 3;
        uint32_t aOff = (uint32_t)(buf * 20480);
        uint32_t bOff = (uint32_t)(buf * 9216);
#pragma unroll
        for (int s = 0; s < 2; s++) {
            uint32_t ah[2][4], al[2][4], bh[2][4], bl[2][4];
#pragma unroll
            for (int mi = 0; mi < 2; mi++) {
                LDSMX4(ah[mi], aB + aOff + mi * 1280 + s * 32);
                LDSMX4(al[mi], aB + aOff + 10240 + mi * 1280 + s * 32);
            }
#pragma unroll
            for (int nbk = 0; nbk < 2; nbk++) {
                LDSMX4T(bh[nbk], bB + bOff + s * 2304 + nbk * 32);
                LDSMX4T(bl[nbk], bB + bOff + 4608 + s * 2304 + nbk * 32);
            }
#pragma unroll
            for (int mi = 0; mi < 2; mi++)
#pragma unroll
                for (int ni = 0; ni < 4; ni++) {
                    uint32_t* fh = &bh[ni >> 1][(ni & 1) * 2];
                    uint32_t* fl = &bl[ni >> 1][(ni & 1) * 2];
                    MMA(acc[mi][ni], ah[mi], fh);
                    MMA(acc[mi][ni], al[mi], fh);
                    MMA(acc[mi][ni], ah[mi], fl);
                }
        }
        if (it + 2 < NIT) {
            G1LD(it + 2, (it + 2) % 3);
            CP_COMMIT();
        }
        if (it + 1 < NIT) {
            if (it + 2 < NIT) { CP_WAIT1(); } else { CP_WAIT0(); }
            __syncthreads();
        }
    }

    float* dst = g_pg1 + (size_t)blockIdx.z * Mm * NB1;
#pragma unroll
    for (int mi = 0; mi < 2; mi++) {
        int r0 = m0 + mw * 32 + mi * 16 + (lane >> 2);
#pragma unroll
        for (int ni = 0; ni < 4; ni++) {
            int col = n0 + nw * 32 + ni * 8 + (lane & 3) * 2;
            *(float2*)&dst[(size_t)r0 * NB1 + col] = make_float2(acc[mi][ni][0], acc[mi][ni][1]);
            *(float2*)&dst[(size_t)(r0 + 8) * NB1 + col] = make_float2(acc[mi][ni][2], acc[mi][ni][3]);
        }
    }
#undef G1LD
}

// sum 4 k-splits -> cg bf16 hi/lo; col 257 = 1.0
__global__ void k_cg_split() {
    int idx = blockIdx.x * 256 + threadIdx.x;
    if (idx >= Mm * KP) return;
    int m = idx / KP, c = idx - m * KP;
    float v = 0.0f;
    if (c < INDIM) {
#pragma unroll
        for (int s = 0; s < 4; s++)
            v += g_pg1[(size_t)s * Mm * NB1 + (size_t)m * NB1 + c];
    } else if (c == INDIM) v = 1.0f;
    bf16 hi, lo; bsplit(v, hi, lo);
    g_cghi[idx] = hi; g_cglo[idx] = lo;
}

__global__ void k_split_W(const float* __restrict__ Wr, const float* __restrict__ Wu,
                          const float* __restrict__ Wc, const float* __restrict__ br,
                          const float* __restrict__ bu, const float* __restrict__ bc) {
    size_t idx = (size_t)blockIdx.x * 256 + threadIdx.x;
    if (idx >= (size_t)3 * 32 * KP * IS) return;
    int n = idx & 127;
    size_t r = idx >> 7;
    int k = (int)(r % KP); r /= KP;
    int d = (int)(r % 32);
    int g = (int)(r / 32);
    const float* W = (g == 0) ? Wr : (g == 1) ? Wu : Wc;
    const float* b = (g == 0) ? br : (g == 1) ? bu : bc;
    float v = 0.0f;
    if (k < INDIM)       v = W[((size_t)d * INDIM + k) * IS + n];
    else if (k == INDIM) v = b[d * IS + n];
    bf16 hi, lo; bsplit(v, hi, lo);
    g_Whi[idx] = hi; g_Wlo[idx] = lo;
}

// ---------------------------------------------------------------------------
// Gate GEMM: A K-slice persistent in smem, B 3-stage pipelined, 2 CTA/SM.
// A smem: hi 0..43008, lo 43008..86016 (336B rows); B at 86016 + buf*9216 (x3).
// dyn smem 113664. 16-row ldmatrix step = 5376.
// ---------------------------------------------------------------------------
__global__ __launch_bounds__(256, 2) void k_mma2(
    const bf16* __restrict__ Ahi, const bf16* __restrict__ Alo,
    const bf16* __restrict__ Whi, const bf16* __restrict__ Wlo,
    const float* __restrict__ q,
    float* __restrict__ out0, float* __restrict__ out1,
    int ngate, int dper) {
    extern __shared__ char sm[];
    __shared__ float qs[128][16];
    uint32_t su = (uint32_t)__cvta_generic_to_shared(sm);
    int t = threadIdx.x, lane = t & 31, wid = t >> 5;
    int n0 = blockIdx.x * 64, m0 = blockIdx.y * 128;
    int gate = blockIdx.z % ngate;
    int rest = blockIdx.z / ngate;
    int kspl = rest & 1, dspl = rest >> 1;
    int d0 = dspl * dper;
    int kc0 = kspl ? 5 : 0, nkc = kspl ? 4 : 5;

    for (int e = t; e < 128 * dper; e += 256)
        qs[e / dper][e % dper] = q[(size_t)(m0 + e / dper) * QDIM + d0 + e % dper];

    int mw = wid >> 1, nw = wid & 1;
    uint32_t aB = su + (uint32_t)((mw * 32 + (lane & 15)) * 336 + (lane >> 4) * 16);
    uint32_t bB = su + 86016u + (uint32_t)((lane & 15) * 144 + (nw * 32 + (lane >> 4) * 8) * 2);

    // load A K-slice once (hi+lo) as its own cp.async group
    int gr = nkc * 4;
#pragma unroll
    for (int pr = 0; pr < 2; pr++) {
        const bf16* sa = pr ? Alo : Ahi;
        for (int g = t; g < 128 * gr; g += 256) {
            int row = g / gr, gg = g - row * gr;
            cpa16(su + (uint32_t)(pr * 43008 + row * 336 + gg * 16),
                  sa + (size_t)(m0 + row) * KP + kc0 * 32 + gg * 8);
        }
    }
    CP_COMMIT();

#define LDB2(JJ, NB)                                                          \
    {                                                                         \
        int _j = (JJ);                                                        \
        int _d = d0 + _j / nkc;                                               \
        int _kc = _j - (_j / nkc) * nkc;                                      \
        size_t _wb = (((size_t)gate * 32 + _d) * KP + (kc0 + _kc) * 32) * IS; \
        int k = t >> 3, gg = t & 7;                                           \
        cpa16(su + (uint32_t)(86016 + (NB) * 9216 + k * 144 + gg * 16),       \
              Whi + _wb + (size_t)k * IS + n0 + gg * 8);                      \
        cpa16(su + (uint32_t)(86016 + (NB) * 9216 + 4608 + k * 144 + gg * 16), \
              Wlo + _wb + (size_t)k * IS + n0 + gg * 8);                      \
    }

    LDB2(0, 0);
    CP_COMMIT();
    LDB2(1, 1);
    CP_COMMIT();
    CP_WAIT1();      // A + B0 complete
    __syncthreads();

    float acc[2][4][4], c[2][4][4];
#pragma unroll
    for (int mi = 0; mi < 2; mi++)
#pragma unroll
        for (int ni = 0; ni < 4; ni++)
#pragma unroll
            for (int j = 0; j < 4; j++) acc[mi][ni][j] = 0.0f;

    const int J = dper * nkc;
    for (int j = 0; j < J; j++) {
        int dj = j / nkc, kc = j - dj * nkc;
        int buf = j % 3;
        uint32_t bOff = (uint32_t)(buf * 9216);
        if (kc == 0) {
#pragma unroll
            for (int mi = 0; mi < 2; mi++)
#pragma unroll
                for (int ni = 0; ni < 4; ni++)
#pragma unroll
                    for (int jj = 0; jj < 4; jj++) c[mi][ni][jj] = 0.0f;
        }
#pragma unroll
        for (int s = 0; s < 2; s++) {
            uint32_t ah[2][4], al[2][4], bh[2][4], bl[2][4];
#pragma unroll
            for (int mi = 0; mi < 2; mi++) {
                LDSMX4(ah[mi], aB + mi * 5376 + kc * 64 + s * 32);
                LDSMX4(al[mi], aB + 43008 + mi * 5376 + kc * 64 + s * 32);
            }
#pragma unroll
            for (int nbk = 0; nbk < 2; nbk++) {
                LDSMX4T(bh[nbk], bB + bOff + s * 2304 + nbk * 32);
                LDSMX4T(bl[nbk], bB + bOff + 4608 + s * 2304 + nbk * 32);
            }
#pragma unroll
            for (int mi = 0; mi < 2; mi++)
#pragma unroll
                for (int ni = 0; ni < 4; ni++) {
                    uint32_t* fh = &bh[ni >> 1][(ni & 1) * 2];
                    uint32_t* fl = &bl[ni >> 1][(ni & 1) * 2];
                    MMA(c[mi][ni], ah[mi], fh);
                    MMA(c[mi][ni], al[mi], fh);
                    MMA(c[mi][ni], ah[mi], fl);
                }
        }
        if (kc == nkc - 1) {
#pragma unroll
            for (int mi = 0; mi < 2; mi++) {
                float q0 = qs[mw * 32 + mi * 16 + (lane >> 2)][dj];
                float q1 = qs[mw * 32 + mi * 16 + 8 + (lane >> 2)][dj];
#pragma unroll
                for (int ni = 0; ni < 4; ni++) {
                    acc[mi][ni][0] = fmaf(q0, c[mi][ni][0], acc[mi][ni][0]);
                    acc[mi][ni][1] = fmaf(q0, c[mi][ni][1], acc[mi][ni][1]);
                    acc[mi][ni][2] = fmaf(q1, c[mi][ni][2], acc[mi][ni][2]);
                    acc[mi][ni][3] = fmaf(q1, c[mi][ni][3], acc[mi][ni][3]);
                }
            }
        }
        if (j + 2 < J) {
            LDB2(j + 2, (j + 2) % 3);
            CP_COMMIT();
        }
        if (j + 1 < J) {
            if (j + 2 < J) { CP_WAIT1(); } else { CP_WAIT0(); }
            __syncthreads();
        }
    }

    float* outp = (gate ? out1 : out0) + (size_t)rest * Mm * IS;
#pragma unroll
    for (int mi = 0; mi < 2; mi++) {
        int r0 = m0 + mw * 32 + mi * 16 + (lane >> 2);
#pragma unroll
        for (int ni = 0; ni < 4; ni++) {
            int col = n0 + nw * 32 + ni * 8 + (lane & 3) * 2;
            *(float2*)&outp[(size_t)r0 * IS + col] = make_float2(acc[mi][ni][0], acc[mi][ni][1]);
            *(float2*)&outp[(size_t)(r0 + 8) * IS + col] = make_float2(acc[mi][ni][2], acc[mi][ni][3]);
        }
    }
#undef LDB2
}

// reduce r,u (4 partials) + sigmoid
__global__ void k_gates_reduce() {
    int idx = blockIdx.x * 256 + threadIdx.x;
    if (idx >= Mm * IS / 4) return;
    const float4* pr = (const float4*)g_pr;
    const float4* pu = (const float4*)g_pu;
    float4 r = make_float4(0.f, 0.f, 0.f, 0.f);
    float4 u = make_float4(0.f, 0.f, 0.f, 0.f);
#pragma unroll
    for (int s = 0; s < 4; s++) {
        float4 a = pr[idx + (size_t)s * (Mm * IS / 4)];
        float4 b = pu[idx + (size_t)s * (Mm * IS / 4)];
        r.x += a.x; r.y += a.y; r.z += a.z; r.w += a.w;
        u.x += b.x; u.y += b.y; u.z += b.z; u.w += b.w;
    }
    r.x = sigmoidf_(r.x); r.y = sigmoidf_(r.y); r.z = sigmoidf_(r.z); r.w = sigmoidf_(r.w);
    u.x = sigmoidf_(u.x); u.y = sigmoidf_(u.y); u.z = sigmoidf_(u.z); u.w = sigmoidf_(u.w);
    ((float4*)g_r)[idx] = r;
    ((float4*)g_u)[idx] = u;
}

__global__ void k_pack_cn_split(const float* __restrict__ x, const float* __restrict__ h,
                                const int* __restrict__ nodes) {
    int idx = blockIdx.x * 256 + threadIdx.x;
    if (idx >= Mm * KP) return;
    int m = idx / KP, c = idx - m * KP;
    float v = 0.0f;
    if (c < XC) {
        v = x[(size_t)nodes[m] * XC + c];
    } else if (c < INDIM) {
        int j = c - XC;
        v = g_r[(size_t)m * IS + j] * h[(size_t)nodes[m] * IS + j];
    } else if (c == INDIM) v = 1.0f;
    bf16 hi, lo; bsplit(v, hi, lo);
    g_cnhi[idx] = hi; g_cnlo[idx] = lo;
}

// reduce candidate (8 partials) + tanh + combine
__global__ void k_final_reduce(const float* __restrict__ h,
                               const int* __restrict__ nodes,
                               float* __restrict__ out) {
    int idx = blockIdx.x * 256 + threadIdx.x;
    if (idx >= Mm * IS / 4) return;
    int m  = idx / (IS / 4);
    int c4 = idx - m * (IS / 4);
    int nm = nodes[m];
    const float4* pc = (const float4*)g_pc;
    float4 c = make_float4(0.f, 0.f, 0.f, 0.f);
#pragma unroll
    for (int s = 0; s < 8; s++) {
        float4 a = pc[idx + (size_t)s * (Mm * IS / 4)];
        c.x += a.x; c.y += a.y; c.z += a.z; c.w += a.w;
    }
    float4 rr = ((const float4*)g_r)[idx];
    float4 uu = ((const float4*)g_u)[idx];
    float4 hv = *(const float4*)&h[(size_t)nm * IS + c4 * 4];
    float4 o;
    o.x = (1.0f - uu.x) * rr.x * hv.x + uu.x * tanhf(c.x);
    o.y = (1.0f - uu.y) * rr.y * hv.y + uu.y * tanhf(c.y);
    o.z = (1.0f - uu.z) * rr.z * hv.z + uu.z * tanhf(c.z);
    o.w = (1.0f - uu.w) * rr.w * hv.w + uu.w * tanhf(c.w);
    *(float4*)&out[(size_t)m * IS + c4 * 4] = o;
}

// ---------------------------------------------------------------------------
extern "C" void kernel_launch(void* const* d_in, const int* in_sizes, int n_in,
                              void* d_out, int out_size) {
    const float* x    = (const float*)d_in[0];
    const float* h    = (const float*)d_in[1];
    const float* q    = (const float*)d_in[2];
    const float* adj  = (const float*)d_in[3];
    const int*   nodes= (const int*)  d_in[4];
    const float* Wu   = (const float*)d_in[5];
    const float* bu   = (const float*)d_in[6];
    const float* Wr   = (const float*)d_in[7];
    const float* br   = (const float*)d_in[8];
    const float* Wc   = (const float*)d_in[9];
    const float* bc   = (const float*)d_in[10];
    float* out = (float*)d_out;

    static bool init = false;
    if (!init) {
        cudaFuncSetAttribute(k_mma_g1, cudaFuncAttributeMaxDynamicSharedMemorySize, 89088);
        cudaFuncSetAttribute(k_mma2, cudaFuncAttributeMaxDynamicSharedMemorySize, 113664);
        init = true;
    }

    bf16 *whi_p, *wlo_p, *cghi_p, *cglo_p, *cnhi_p, *cnlo_p;
    cudaGetSymbolAddress((void**)&whi_p, g_Whi);
    cudaGetSymbolAddress((void**)&wlo_p, g_Wlo);
    cudaGetSymbolAddress((void**)&cghi_p, g_cghi);
    cudaGetSymbolAddress((void**)&cglo_p, g_cglo);
    cudaGetSymbolAddress((void**)&cnhi_p, g_cnhi);
    cudaGetSymbolAddress((void**)&cnlo_p, g_cnlo);
    float *pr_p, *pu_p, *pc_p;
    cudaGetSymbolAddress((void**)&pr_p, g_pr);
    cudaGetSymbolAddress((void**)&pu_p, g_pu);
    cudaGetSymbolAddress((void**)&pc_p, g_pc);

    k_cat_split<<<(Nn * NB1 + 255) / 256, 256>>>(x, h);
    k_adj_split<<<(Mm * Nn / 4 + 255) / 256, 256>>>(adj, nodes);
    k_split_W<<<(int)(((size_t)3 * 32 * KP * IS + 255) / 256), 256>>>(Wr, Wu, Wc, br, bu, bc);
    k_mma_g1<<<dim3(5, 16, 4), 256, 89088>>>();
    k_cg_split<<<(Mm * KP + 255) / 256, 256>>>();
    // gates r+u: z = gate(2) x (kspl(2) x dspl(2)), dper=16 -> 256 CTAs
    k_mma2<<<dim3(2, 16, 8), 256, 113664>>>(cghi_p, cglo_p, whi_p, wlo_p, q, pr_p, pu_p, 2, 16);
    k_gates_reduce<<<(Mm * IS / 4 + 255) / 256, 256>>>();
    k_pack_cn_split<<<(Mm * KP + 255) / 256, 256>>>(x, h, nodes);
    // candidate: z = kspl(2) x dspl(4), dper=8 -> 256 CTAs
    k_mma2<<<dim3(2, 16, 8), 256, 113664>>>(cnhi_p, cnlo_p,
                                            whi_p + (size_t)2 * 32 * KP * IS,
                                            wlo_p + (size_t)2 * 32 * KP * IS,
                                            q, pc_p, pc_p, 1, 8);
    k_final_reduce<<<(Mm * IS / 4 + 255) / 256, 256>>>(h, nodes, out);
}

// round 13
// speedup vs baseline: 1.1153x; 1.1153x over previous
#include <cuda_runtime.h>
#include <cuda_bf16.h>
#include <math.h>
#include <stdint.h>

#define Nn   4096
#define Mm   2048
#define IS   128
#define XC   129
#define INDIM 257
#define QDIM 32
#define KP   288      // gate-GEMM K (257 + bias col + pad)
#define NB1  320      // gemm1 out width

typedef unsigned long long ull;
typedef __nv_bfloat16 bf16;

// Scratch
__device__ __align__(16) bf16 g_cbhi[Nn * NB1];
__device__ __align__(16) bf16 g_cblo[Nn * NB1];
__device__ __align__(16) bf16 g_ajhi[Mm * Nn];
__device__ __align__(16) bf16 g_ajlo[Mm * Nn];
__device__ float g_pg1 [4 * Mm * NB1];
__device__ __align__(16) bf16 g_cghi[Mm * KP];
__device__ __align__(16) bf16 g_cglo[Mm * KP];
__device__ __align__(16) bf16 g_cnhi[Mm * KP];
__device__ __align__(16) bf16 g_cnlo[Mm * KP];
__device__ __align__(16) bf16 g_Whi[(size_t)3 * 32 * KP * IS];
__device__ __align__(16) bf16 g_Wlo[(size_t)3 * 32 * KP * IS];
__device__ float g_pr [4 * Mm * IS];
__device__ float g_pu [4 * Mm * IS];
__device__ float g_pc [8 * Mm * IS];
__device__ float g_r  [Mm * IS];
__device__ float g_u  [Mm * IS];

__device__ __forceinline__ float sigmoidf_(float v) { return 1.0f / (1.0f + expf(-v)); }
__device__ __forceinline__ void cpa16(uint32_t dst, const void* src) {
    asm volatile("cp.async.ca.shared.global [%0], [%1], 16;" :: "r"(dst), "l"(src));
}
#define CP_COMMIT() asm volatile("cp.async.commit_group;")
#define CP_WAIT0()  asm volatile("cp.async.wait_group 0;")
#define CP_WAIT1()  asm volatile("cp.async.wait_group 1;")

#define LDSMX4(R, ADDR)                                                       \
    asm volatile("ldmatrix.sync.aligned.m8n8.x4.shared.b16 {%0,%1,%2,%3}, [%4];" \
        : "=r"((R)[0]), "=r"((R)[1]), "=r"((R)[2]), "=r"((R)[3]) : "r"(ADDR))
#define LDSMX4T(R, ADDR)                                                      \
    asm volatile("ldmatrix.sync.aligned.m8n8.x4.trans.shared.b16 {%0,%1,%2,%3}, [%4];" \
        : "=r"((R)[0]), "=r"((R)[1]), "=r"((R)[2]), "=r"((R)[3]) : "r"(ADDR))
#define MMA(C, A, B)                                                          \
    asm volatile("mma.sync.aligned.m16n8k16.row.col.f32.bf16.bf16.f32 "       \
        "{%0,%1,%2,%3}, {%4,%5,%6,%7}, {%8,%9}, {%0,%1,%2,%3};"               \
        : "+f"((C)[0]), "+f"((C)[1]), "+f"((C)[2]), "+f"((C)[3])              \
        : "r"((A)[0]), "r"((A)[1]), "r"((A)[2]), "r"((A)[3]),                 \
          "r"((B)[0]), "r"((B)[1]))

__device__ __forceinline__ void bsplit(float v, bf16& hi, bf16& lo) {
    hi = __float2bfloat16(v);
    lo = __float2bfloat16(v - __bfloat162float(hi));
}

// ---------------------------------------------------------------------------
__global__ void k_cat_split(const float* __restrict__ x, const float* __restrict__ h) {
    int idx = blockIdx.x * 256 + threadIdx.x;
    if (idx >= Nn * NB1) return;
    int row = idx / NB1, c = idx - row * NB1;
    float v = 0.0f;
    if (c < XC)        v = x[row * XC + c];
    else if (c < INDIM) v = h[row * IS + (c - XC)];
    bf16 hi, lo; bsplit(v, hi, lo);
    g_cbhi[idx] = hi; g_cblo[idx] = lo;
}

__global__ void k_adj_split(const float* __restrict__ adj, const int* __restrict__ nodes) {
    int i4 = blockIdx.x * 256 + threadIdx.x;
    if (i4 >= Mm * Nn / 4) return;
    int m = i4 >> 10;
    int k4 = (i4 & 1023) * 4;
    float4 v = *(const float4*)&adj[(size_t)nodes[m] * Nn + k4];
    bf16 h[4], l[4];
    bsplit(v.x, h[0], l[0]); bsplit(v.y, h[1], l[1]);
    bsplit(v.z, h[2], l[2]); bsplit(v.w, h[3], l[3]);
    *(ull*)&g_ajhi[(size_t)m * Nn + k4] = *(ull*)h;
    *(ull*)&g_ajlo[(size_t)m * Nn + k4] = *(ull*)l;
}

// ---------------------------------------------------------------------------
// Tensor GEMM1: BM=128, BN=64, K-split 4. grid (5, 16, 4), 2 CTA/SM.
// 3-stage cp.async pipeline: A buf 20480B x3 at 0, B buf 9216B x3 at 61440.
// dyn smem 89088.
// ---------------------------------------------------------------------------
__global__ __launch_bounds__(256, 2) void k_mma_g1() {
    extern __shared__ char sm[];
    uint32_t su = (uint32_t)__cvta_generic_to_shared(sm);
    int t = threadIdx.x, lane = t & 31, wid = t >> 5;
    int n0 = blockIdx.x * 64, m0 = blockIdx.y * 128, ks = blockIdx.z * 1024;
    int mw = wid >> 1, nw = wid & 1;
    uint32_t aB = su + (uint32_t)((mw * 32 + (lane & 15)) * 80 + (lane >> 4) * 16);
    uint32_t bB = su + 61440u + (uint32_t)((lane & 15) * 144 + (nw * 32 + (lane >> 4) * 8) * 2);

    float acc[2][4][4];
#pragma unroll
    for (int mi = 0; mi < 2; mi++)
#pragma unroll
        for (int ni = 0; ni < 4; ni++)
#pragma unroll
            for (int j = 0; j < 4; j++) acc[mi][ni][j] = 0.0f;

#define G1LD(KC, NB)                                                          \
    {                                                                         \
        int _k0 = ks + (KC) * 32;                                             \
        _Pragma("unroll")                                                     \
        for (int pr = 0; pr < 2; pr++) {                                      \
            const bf16* sa = pr ? g_ajlo : g_ajhi;                            \
            _Pragma("unroll")                                                 \
            for (int p = 0; p < 2; p++) {                                     \
                int e = t + 256 * p;                                          \
                int row = e >> 2, gg = e & 3;                                 \
                cpa16(su + (uint32_t)((NB) * 20480 + pr * 10240 + row * 80 + gg * 16), \
                      sa + (size_t)(m0 + row) * Nn + _k0 + gg * 8);           \
            }                                                                 \
            const bf16* sb = pr ? g_cblo : g_cbhi;                            \
            int k = t >> 3, gg2 = t & 7;                                      \
            cpa16(su + (uint32_t)(61440 + (NB) * 9216 + pr * 4608 + k * 144 + gg2 * 16), \
                  sb + (size_t)(_k0 + k) * NB1 + n0 + gg2 * 8);               \
        }                                                                     \
    }

    G1LD(0, 0);
    CP_COMMIT();
    G1LD(1, 1);
    CP_COMMIT();
    CP_WAIT1();
    __syncthreads();

    const int NIT = 32;
    for (int it = 0; it < NIT; it++) {
        int buf = it % 3;
        uint32_t aOff = (uint32_t)(buf * 20480);
        uint32_t bOff = (uint32_t)(buf * 9216);
#pragma unroll
        for (int s = 0; s < 2; s++) {
            uint32_t ah[2][4], al[2][4], bh[2][4], bl[2][4];
#pragma unroll
            for (int mi = 0; mi < 2; mi++) {
                LDSMX4(ah[mi], aB + aOff + mi * 1280 + s * 32);
                LDSMX4(al[mi], aB + aOff + 10240 + mi * 1280 + s * 32);
            }
#pragma unroll
            for (int nbk = 0; nbk < 2; nbk++) {
                LDSMX4T(bh[nbk], bB + bOff + s * 2304 + nbk * 32);
                LDSMX4T(bl[nbk], bB + bOff + 4608 + s * 2304 + nbk * 32);
            }
#pragma unroll
            for (int mi = 0; mi < 2; mi++)
#pragma unroll
                for (int ni = 0; ni < 4; ni++) {
                    uint32_t* fh = &bh[ni >> 1][(ni & 1) * 2];
                    uint32_t* fl = &bl[ni >> 1][(ni & 1) * 2];
                    MMA(acc[mi][ni], ah[mi], fh);
                    MMA(acc[mi][ni], al[mi], fh);
                    MMA(acc[mi][ni], ah[mi], fl);
                }
        }
        if (it + 2 < NIT) {
            G1LD(it + 2, (it + 2) % 3);
            CP_COMMIT();
        }
        if (it + 1 < NIT) {
            if (it + 2 < NIT) { CP_WAIT1(); } else { CP_WAIT0(); }
            __syncthreads();
        }
    }

    float* dst = g_pg1 + (size_t)blockIdx.z * Mm * NB1;
#pragma unroll
    for (int mi = 0; mi < 2; mi++) {
        int r0 = m0 + mw * 32 + mi * 16 + (lane >> 2);
#pragma unroll
        for (int ni = 0; ni < 4; ni++) {
            int col = n0 + nw * 32 + ni * 8 + (lane & 3) * 2;
            *(float2*)&dst[(size_t)r0 * NB1 + col] = make_float2(acc[mi][ni][0], acc[mi][ni][1]);
            *(float2*)&dst[(size_t)(r0 + 8) * NB1 + col] = make_float2(acc[mi][ni][2], acc[mi][ni][3]);
        }
    }
#undef G1LD
}

// sum 4 k-splits -> cg bf16 hi/lo; col 257 = 1.0
__global__ void k_cg_split() {
    int idx = blockIdx.x * 256 + threadIdx.x;
    if (idx >= Mm * KP) return;
    int m = idx / KP, c = idx - m * KP;
    float v = 0.0f;
    if (c < INDIM) {
#pragma unroll
        for (int s = 0; s < 4; s++)
            v += g_pg1[(size_t)s * Mm * NB1 + (size_t)m * NB1 + c];
    } else if (c == INDIM) v = 1.0f;
    bf16 hi, lo; bsplit(v, hi, lo);
    g_cghi[idx] = hi; g_cglo[idx] = lo;
}

__global__ void k_split_W(const float* __restrict__ Wr, const float* __restrict__ Wu,
                          const float* __restrict__ Wc, const float* __restrict__ br,
                          const float* __restrict__ bu, const float* __restrict__ bc) {
    size_t idx = (size_t)blockIdx.x * 256 + threadIdx.x;
    if (idx >= (size_t)3 * 32 * KP * IS) return;
    int n = idx & 127;
    size_t r = idx >> 7;
    int k = (int)(r % KP); r /= KP;
    int d = (int)(r % 32);
    int g = (int)(r / 32);
    const float* W = (g == 0) ? Wr : (g == 1) ? Wu : Wc;
    const float* b = (g == 0) ? br : (g == 1) ? bu : bc;
    float v = 0.0f;
    if (k < INDIM)       v = W[((size_t)d * INDIM + k) * IS + n];
    else if (k == INDIM) v = b[d * IS + n];
    bf16 hi, lo; bsplit(v, hi, lo);
    g_Whi[idx] = hi; g_Wlo[idx] = lo;
}

// ---------------------------------------------------------------------------
// Gate GEMM: A K-slice persistent in smem, B double-buffered, 2 CTA/SM.
// z = gate + ngate*(kspl + 2*dspl). kspl0: chunks 0-4, kspl1: chunks 5-8.
// A smem: hi 0..43008, lo 43008..86016 (336B rows); B at 86016 + buf*9216 (x2).
// dyn smem 104448 (+8192 static qs = 112.6KB -> 2 CTA/SM).
// ---------------------------------------------------------------------------
__global__ __launch_bounds__(256, 2) void k_mma2(
    const bf16* __restrict__ Ahi, const bf16* __restrict__ Alo,
    const bf16* __restrict__ Whi, const bf16* __restrict__ Wlo,
    const float* __restrict__ q,
    float* __restrict__ out0, float* __restrict__ out1,
    int ngate, int dper) {
    extern __shared__ char sm[];
    __shared__ float qs[128][16];
    uint32_t su = (uint32_t)__cvta_generic_to_shared(sm);
    int t = threadIdx.x, lane = t & 31, wid = t >> 5;
    int n0 = blockIdx.x * 64, m0 = blockIdx.y * 128;
    int gate = blockIdx.z % ngate;
    int rest = blockIdx.z / ngate;
    int kspl = rest & 1, dspl = rest >> 1;
    int d0 = dspl * dper;
    int kc0 = kspl ? 5 : 0, nkc = kspl ? 4 : 5;

    for (int e = t; e < 128 * dper; e += 256)
        qs[e / dper][e % dper] = q[(size_t)(m0 + e / dper) * QDIM + d0 + e % dper];

    int mw = wid >> 1, nw = wid & 1;
    uint32_t aB = su + (uint32_t)((mw * 32 + (lane & 15)) * 336 + (lane >> 4) * 16);
    uint32_t bB = su + 86016u + (uint32_t)((lane & 15) * 144 + (nw * 32 + (lane >> 4) * 8) * 2);

    // load A K-slice once (hi+lo)
    int gr = nkc * 4;   // 16B granules per row
#pragma unroll
    for (int pr = 0; pr < 2; pr++) {
        const bf16* sa = pr ? Alo : Ahi;
        for (int g = t; g < 128 * gr; g += 256) {
            int row = g / gr, gg = g - row * gr;
            cpa16(su + (uint32_t)(pr * 43008 + row * 336 + gg * 16),
                  sa + (size_t)(m0 + row) * KP + kc0 * 32 + gg * 8);
        }
    }

#define LDB2(DJ, KC, NB)                                                      \
    {                                                                         \
        int _d = d0 + (DJ);                                                   \
        size_t _wb = (((size_t)gate * 32 + _d) * KP + (kc0 + (KC)) * 32) * IS; \
        int k = t >> 3, gg = t & 7;                                           \
        cpa16(su + (uint32_t)(86016 + (NB) * 9216 + k * 144 + gg * 16),       \
              Whi + _wb + (size_t)k * IS + n0 + gg * 8);                      \
        cpa16(su + (uint32_t)(86016 + (NB) * 9216 + 4608 + k * 144 + gg * 16), \
              Wlo + _wb + (size_t)k * IS + n0 + gg * 8);                      \
    }

    LDB2(0, 0, 0);
    CP_COMMIT();
    CP_WAIT0();
    __syncthreads();

    float acc[2][4][4], c[2][4][4];
#pragma unroll
    for (int mi = 0; mi < 2; mi++)
#pragma unroll
        for (int ni = 0; ni < 4; ni++)
#pragma unroll
            for (int j = 0; j < 4; j++) acc[mi][ni][j] = 0.0f;

    const int J = dper * nkc;
    for (int j = 0; j < J; j++) {
        int dj = j / nkc, kc = j - dj * nkc;
        int buf = j & 1, nb = buf ^ 1;
        if (kc == 0) {
#pragma unroll
            for (int mi = 0; mi < 2; mi++)
#pragma unroll
                for (int ni = 0; ni < 4; ni++)
#pragma unroll
                    for (int jj = 0; jj < 4; jj++) c[mi][ni][jj] = 0.0f;
        }
        if (j + 1 < J) {
            int j2 = j + 1, dj2 = j2 / nkc, kc2 = j2 - dj2 * nkc;
            LDB2(dj2, kc2, nb);
            CP_COMMIT();
        }
#pragma unroll
        for (int s = 0; s < 2; s++) {
            uint32_t ah[2][4], al[2][4], bh[2][4], bl[2][4];
#pragma unroll
            for (int mi = 0; mi < 2; mi++) {
                LDSMX4(ah[mi], aB + mi * 5376 + kc * 64 + s * 32);
                LDSMX4(al[mi], aB + 43008 + mi * 5376 + kc * 64 + s * 32);
            }
#pragma unroll
            for (int nbk = 0; nbk < 2; nbk++) {
                LDSMX4T(bh[nbk], bB + buf * 9216 + s * 2304 + nbk * 32);
                LDSMX4T(bl[nbk], bB + buf * 9216 + 4608 + s * 2304 + nbk * 32);
            }
#pragma unroll
            for (int mi = 0; mi < 2; mi++)
#pragma unroll
                for (int ni = 0; ni < 4; ni++) {
                    uint32_t* fh = &bh[ni >> 1][(ni & 1) * 2];
                    uint32_t* fl = &bl[ni >> 1][(ni & 1) * 2];
                    MMA(c[mi][ni], ah[mi], fh);
                    MMA(c[mi][ni], al[mi], fh);
                    MMA(c[mi][ni], ah[mi], fl);
                }
        }
        if (kc == nkc - 1) {
#pragma unroll
            for (int mi = 0; mi < 2; mi++) {
                float q0 = qs[mw * 32 + mi * 16 + (lane >> 2)][dj];
                float q1 = qs[mw * 32 + mi * 16 + 8 + (lane >> 2)][dj];
#pragma unroll
                for (int ni = 0; ni < 4; ni++) {
                    acc[mi][ni][0] = fmaf(q0, c[mi][ni][0], acc[mi][ni][0]);
                    acc[mi][ni][1] = fmaf(q0, c[mi][ni][1], acc[mi][ni][1]);
                    acc[mi][ni][2] = fmaf(q1, c[mi][ni][2], acc[mi][ni][2]);
                    acc[mi][ni][3] = fmaf(q1, c[mi][ni][3], acc[mi][ni][3]);
                }
            }
        }
        CP_WAIT0();
        __syncthreads();
    }

    float* outp = (gate ? out1 : out0) + (size_t)rest * Mm * IS;
#pragma unroll
    for (int mi = 0; mi < 2; mi++) {
        int r0 = m0 + mw * 32 + mi * 16 + (lane >> 2);
#pragma unroll
        for (int ni = 0; ni < 4; ni++) {
            int col = n0 + nw * 32 + ni * 8 + (lane & 3) * 2;
            *(float2*)&outp[(size_t)r0 * IS + col] = make_float2(acc[mi][ni][0], acc[mi][ni][1]);
            *(float2*)&outp[(size_t)(r0 + 8) * IS + col] = make_float2(acc[mi][ni][2], acc[mi][ni][3]);
        }
    }
#undef LDB2
}

// reduce r,u (4 partials) + sigmoid
__global__ void k_gates_reduce() {
    int idx = blockIdx.x * 256 + threadIdx.x;
    if (idx >= Mm * IS / 4) return;
    const float4* pr = (const float4*)g_pr;
    const float4* pu = (const float4*)g_pu;
    float4 r = make_float4(0.f, 0.f, 0.f, 0.f);
    float4 u = make_float4(0.f, 0.f, 0.f, 0.f);
#pragma unroll
    for (int s = 0; s < 4; s++) {
        float4 a = pr[idx + (size_t)s * (Mm * IS / 4)];
        float4 b = pu[idx + (size_t)s * (Mm * IS / 4)];
        r.x += a.x; r.y += a.y; r.z += a.z; r.w += a.w;
        u.x += b.x; u.y += b.y; u.z += b.z; u.w += b.w;
    }
    r.x = sigmoidf_(r.x); r.y = sigmoidf_(r.y); r.z = sigmoidf_(r.z); r.w = sigmoidf_(r.w);
    u.x = sigmoidf_(u.x); u.y = sigmoidf_(u.y); u.z = sigmoidf_(u.z); u.w = sigmoidf_(u.w);
    ((float4*)g_r)[idx] = r;
    ((float4*)g_u)[idx] = u;
}

__global__ void k_pack_cn_split(const float* __restrict__ x, const float* __restrict__ h,
                                const int* __restrict__ nodes) {
    int idx = blockIdx.x * 256 + threadIdx.x;
    if (idx >= Mm * KP) return;
    int m = idx / KP, c = idx - m * KP;
    float v = 0.0f;
    if (c < XC) {
        v = x[(size_t)nodes[m] * XC + c];
    } else if (c < INDIM) {
        int j = c - XC;
        v = g_r[(size_t)m * IS + j] * h[(size_t)nodes[m] * IS + j];
    } else if (c == INDIM) v = 1.0f;
    bf16 hi, lo; bsplit(v, hi, lo);
    g_cnhi[idx] = hi; g_cnlo[idx] = lo;
}

// reduce candidate (8 partials) + tanh + combine
__global__ void k_final_reduce(const float* __restrict__ h,
                               const int* __restrict__ nodes,
                               float* __restrict__ out) {
    int idx = blockIdx.x * 256 + threadIdx.x;
    if (idx >= Mm * IS / 4) return;
    int m  = idx / (IS / 4);
    int c4 = idx - m * (IS / 4);
    int nm = nodes[m];
    const float4* pc = (const float4*)g_pc;
    float4 c = make_float4(0.f, 0.f, 0.f, 0.f);
#pragma unroll
    for (int s = 0; s < 8; s++) {
        float4 a = pc[idx + (size_t)s * (Mm * IS / 4)];
        c.x += a.x; c.y += a.y; c.z += a.z; c.w += a.w;
    }
    float4 rr = ((const float4*)g_r)[idx];
    float4 uu = ((const float4*)g_u)[idx];
    float4 hv = *(const float4*)&h[(size_t)nm * IS + c4 * 4];
    float4 o;
    o.x = (1.0f - uu.x) * rr.x * hv.x + uu.x * tanhf(c.x);
    o.y = (1.0f - uu.y) * rr.y * hv.y + uu.y * tanhf(c.y);
    o.z = (1.0f - uu.z) * rr.z * hv.z + uu.z * tanhf(c.z);
    o.w = (1.0f - uu.w) * rr.w * hv.w + uu.w * tanhf(c.w);
    *(float4*)&out[(size_t)m * IS + c4 * 4] = o;
}

// ---------------------------------------------------------------------------
extern "C" void kernel_launch(void* const* d_in, const int* in_sizes, int n_in,
                              void* d_out, int out_size) {
    const float* x    = (const float*)d_in[0];
    const float* h    = (const float*)d_in[1];
    const float* q    = (const float*)d_in[2];
    const float* adj  = (const float*)d_in[3];
    const int*   nodes= (const int*)  d_in[4];
    const float* Wu   = (const float*)d_in[5];
    const float* bu   = (const float*)d_in[6];
    const float* Wr   = (const float*)d_in[7];
    const float* br   = (const float*)d_in[8];
    const float* Wc   = (const float*)d_in[9];
    const float* bc   = (const float*)d_in[10];
    float* out = (float*)d_out;

    static bool init = false;
    if (!init) {
        cudaFuncSetAttribute(k_mma_g1, cudaFuncAttributeMaxDynamicSharedMemorySize, 89088);
        cudaFuncSetAttribute(k_mma2, cudaFuncAttributeMaxDynamicSharedMemorySize, 104448);
        init = true;
    }

    bf16 *whi_p, *wlo_p, *cghi_p, *cglo_p, *cnhi_p, *cnlo_p;
    cudaGetSymbolAddress((void**)&whi_p, g_Whi);
    cudaGetSymbolAddress((void**)&wlo_p, g_Wlo);
    cudaGetSymbolAddress((void**)&cghi_p, g_cghi);
    cudaGetSymbolAddress((void**)&cglo_p, g_cglo);
    cudaGetSymbolAddress((void**)&cnhi_p, g_cnhi);
    cudaGetSymbolAddress((void**)&cnlo_p, g_cnlo);
    float *pr_p, *pu_p, *pc_p;
    cudaGetSymbolAddress((void**)&pr_p, g_pr);
    cudaGetSymbolAddress((void**)&pu_p, g_pu);
    cudaGetSymbolAddress((void**)&pc_p, g_pc);

    k_cat_split<<<(Nn * NB1 + 255) / 256, 256>>>(x, h);
    k_adj_split<<<(Mm * Nn / 4 + 255) / 256, 256>>>(adj, nodes);
    k_split_W<<<(int)(((size_t)3 * 32 * KP * IS + 255) / 256), 256>>>(Wr, Wu, Wc, br, bu, bc);
    k_mma_g1<<<dim3(5, 16, 4), 256, 89088>>>();
    k_cg_split<<<(Mm * KP + 255) / 256, 256>>>();
    // gates r+u: z = gate(2) x (kspl(2) x dspl(2)), dper=16 -> 256 CTAs
    k_mma2<<<dim3(2, 16, 8), 256, 104448>>>(cghi_p, cglo_p, whi_p, wlo_p, q, pr_p, pu_p, 2, 16);
    k_gates_reduce<<<(Mm * IS / 4 + 255) / 256, 256>>>();
    k_pack_cn_split<<<(Mm * KP + 255) / 256, 256>>>(x, h, nodes);
    // candidate: z = kspl(2) x dspl(4), dper=8 -> 256 CTAs
    k_mma2<<<dim3(2, 16, 8), 256, 104448>>>(cnhi_p, cnlo_p,
                                            whi_p + (size_t)2 * 32 * KP * IS,
                                            wlo_p + (size_t)2 * 32 * KP * IS,
                                            q, pc_p, pc_p, 1, 8);
    k_final_reduce<<<(Mm * IS / 4 + 255) / 256, 256>>>(h, nodes, out);
}

// round 14
// speedup vs baseline: 1.1706x; 1.0496x over previous
#include <cuda_runtime.h>
#include <cuda_bf16.h>
#include <math.h>
#include <stdint.h>

#define Nn   4096
#define Mm   2048
#define IS   128
#define XC   129
#define INDIM 257
#define QDIM 32
#define KP   288      // gate-GEMM K (257 + bias col + pad)
#define NB1  320      // gemm1 out width

typedef unsigned long long ull;
typedef __nv_bfloat16 bf16;

// Scratch
__device__ __align__(16) bf16 g_cbhi[Nn * NB1];
__device__ __align__(16) bf16 g_cblo[Nn * NB1];
__device__ __align__(16) bf16 g_ajhi[Mm * Nn];
__device__ __align__(16) bf16 g_ajlo[Mm * Nn];
__device__ float g_pg1 [4 * Mm * NB1];
__device__ __align__(16) bf16 g_cghi[Mm * KP];
__device__ __align__(16) bf16 g_cglo[Mm * KP];
__device__ __align__(16) bf16 g_cnhi[Mm * KP];
__device__ __align__(16) bf16 g_cnlo[Mm * KP];
__device__ __align__(16) bf16 g_Whi[(size_t)3 * 32 * KP * IS];
__device__ __align__(16) bf16 g_Wlo[(size_t)3 * 32 * KP * IS];
__device__ float g_pr [4 * Mm * IS];
__device__ float g_pu [4 * Mm * IS];
__device__ float g_pc [8 * Mm * IS];
__device__ float g_r  [Mm * IS];
__device__ float g_u  [Mm * IS];

__device__ __forceinline__ float sigmoidf_(float v) { return 1.0f / (1.0f + expf(-v)); }
__device__ __forceinline__ void cpa16(uint32_t dst, const void* src) {
    asm volatile("cp.async.ca.shared.global [%0], [%1], 16;" :: "r"(dst), "l"(src));
}
#define CP_COMMIT() asm volatile("cp.async.commit_group;")
#define CP_WAIT0()  asm volatile("cp.async.wait_group 0;")
#define CP_WAIT1()  asm volatile("cp.async.wait_group 1;")

#define LDSMX4(R, ADDR)                                                       \
    asm volatile("ldmatrix.sync.aligned.m8n8.x4.shared.b16 {%0,%1,%2,%3}, [%4];" \
        : "=r"((R)[0]), "=r"((R)[1]), "=r"((R)[2]), "=r"((R)[3]) : "r"(ADDR))
#define LDSMX4T(R, ADDR)                                                      \
    asm volatile("ldmatrix.sync.aligned.m8n8.x4.trans.shared.b16 {%0,%1,%2,%3}, [%4];" \
        : "=r"((R)[0]), "=r"((R)[1]), "=r"((R)[2]), "=r"((R)[3]) : "r"(ADDR))
#define MMA(C, A, B)                                                          \
    asm volatile("mma.sync.aligned.m16n8k16.row.col.f32.bf16.bf16.f32 "       \
        "{%0,%1,%2,%3}, {%4,%5,%6,%7}, {%8,%9}, {%0,%1,%2,%3};"               \
        : "+f"((C)[0]), "+f"((C)[1]), "+f"((C)[2]), "+f"((C)[3])              \
        : "r"((A)[0]), "r"((A)[1]), "r"((A)[2]), "r"((A)[3]),                 \
          "r"((B)[0]), "r"((B)[1]))

__device__ __forceinline__ void bsplit(float v, bf16& hi, bf16& lo) {
    hi = __float2bfloat16(v);
    lo = __float2bfloat16(v - __bfloat162float(hi));
}

// ---------------------------------------------------------------------------
// Fused prep: [0,640) cat-split, [640,8832) adj-split, [8832,10560) W-split.
// All stores are 16B (8 bf16) vectors.
// ---------------------------------------------------------------------------
#define PREP_CAT_BLKS 640     // Nn*40 / 256
#define PREP_ADJ_BLKS 8192    // Mm*Nn/4 / 256
#define PREP_W_BLKS   1728    // 3*32*288*16 / 256

__global__ void k_prep(const float* __restrict__ x, const float* __restrict__ h,
                       const float* __restrict__ adj, const int* __restrict__ nodes,
                       const float* __restrict__ Wr, const float* __restrict__ Wu,
                       const float* __restrict__ Wc, const float* __restrict__ br,
                       const float* __restrict__ bu, const float* __restrict__ bc) {
    int b = blockIdx.x, t = threadIdx.x;
    if (b < PREP_CAT_BLKS) {
        int idx = b * 256 + t;                   // over Nn*40
        int row = idx / 40, c0 = (idx - row * 40) * 8;
        bf16 hv[8], lv[8];
#pragma unroll
        for (int j = 0; j < 8; j++) {
            int c = c0 + j;
            float v = 0.0f;
            if (c < XC)        v = x[row * XC + c];
            else if (c < INDIM) v = h[row * IS + (c - XC)];
            bsplit(v, hv[j], lv[j]);
        }
        size_t o = (size_t)row * NB1 + c0;
        *(ull*)&g_cbhi[o] = *(ull*)hv;  *(ull*)&g_cbhi[o + 4] = *(ull*)(hv + 4);
        *(ull*)&g_cblo[o] = *(ull*)lv;  *(ull*)&g_cblo[o + 4] = *(ull*)(lv + 4);
    } else if (b < PREP_CAT_BLKS + PREP_ADJ_BLKS) {
        int i4 = (b - PREP_CAT_BLKS) * 256 + t;  // over Mm*Nn/4
        int m = i4 >> 10;
        int k4 = (i4 & 1023) * 4;
        float4 v = *(const float4*)&adj[(size_t)nodes[m] * Nn + k4];
        bf16 hh[4], ll[4];
        bsplit(v.x, hh[0], ll[0]); bsplit(v.y, hh[1], ll[1]);
        bsplit(v.z, hh[2], ll[2]); bsplit(v.w, hh[3], ll[3]);
        *(ull*)&g_ajhi[(size_t)m * Nn + k4] = *(ull*)hh;
        *(ull*)&g_ajlo[(size_t)m * Nn + k4] = *(ull*)ll;
    } else {
        int idx = (b - PREP_CAT_BLKS - PREP_ADJ_BLKS) * 256 + t;  // over 3*32*288*16
        int n8 = idx & 15;
        int r = idx >> 4;
        int k = r % KP; r /= KP;
        int d = r % 32;
        int g = r / 32;
        const float* W = (g == 0) ? Wr : (g == 1) ? Wu : Wc;
        const float* bb = (g == 0) ? br : (g == 1) ? bu : bc;
        bf16 hv[8], lv[8];
        if (k < INDIM) {
            const float* src = &W[((size_t)d * INDIM + k) * IS + n8 * 8];
            float4 a0 = *(const float4*)src;
            float4 a1 = *(const float4*)(src + 4);
            bsplit(a0.x, hv[0], lv[0]); bsplit(a0.y, hv[1], lv[1]);
            bsplit(a0.z, hv[2], lv[2]); bsplit(a0.w, hv[3], lv[3]);
            bsplit(a1.x, hv[4], lv[4]); bsplit(a1.y, hv[5], lv[5]);
            bsplit(a1.z, hv[6], lv[6]); bsplit(a1.w, hv[7], lv[7]);
        } else if (k == INDIM) {
            const float* src = &bb[d * IS + n8 * 8];
            float4 a0 = *(const float4*)src;
            float4 a1 = *(const float4*)(src + 4);
            bsplit(a0.x, hv[0], lv[0]); bsplit(a0.y, hv[1], lv[1]);
            bsplit(a0.z, hv[2], lv[2]); bsplit(a0.w, hv[3], lv[3]);
            bsplit(a1.x, hv[4], lv[4]); bsplit(a1.y, hv[5], lv[5]);
            bsplit(a1.z, hv[6], lv[6]); bsplit(a1.w, hv[7], lv[7]);
        } else {
#pragma unroll
            for (int j = 0; j < 8; j++) { hv[j] = __float2bfloat16(0.f); lv[j] = hv[j]; }
        }
        size_t o = ((size_t)(g * 32 + d) * KP + k) * IS + n8 * 8;
        *(ull*)&g_Whi[o] = *(ull*)hv;  *(ull*)&g_Whi[o + 4] = *(ull*)(hv + 4);
        *(ull*)&g_Wlo[o] = *(ull*)lv;  *(ull*)&g_Wlo[o + 4] = *(ull*)(lv + 4);
    }
}

// ---------------------------------------------------------------------------
// Tensor GEMM1: BM=128, BN=64, K-split 4. grid (5, 16, 4), 2 CTA/SM.
// 3-stage cp.async pipeline. dyn smem 89088.
// ---------------------------------------------------------------------------
__global__ __launch_bounds__(256, 2) void k_mma_g1() {
    extern __shared__ char sm[];
    uint32_t su = (uint32_t)__cvta_generic_to_shared(sm);
    int t = threadIdx.x, lane = t & 31, wid = t >> 5;
    int n0 = blockIdx.x * 64, m0 = blockIdx.y * 128, ks = blockIdx.z * 1024;
    int mw = wid >> 1, nw = wid & 1;
    uint32_t aB = su + (uint32_t)((mw * 32 + (lane & 15)) * 80 + (lane >> 4) * 16);
    uint32_t bB = su + 61440u + (uint32_t)((lane & 15) * 144 + (nw * 32 + (lane >> 4) * 8) * 2);

    float acc[2][4][4];
#pragma unroll
    for (int mi = 0; mi < 2; mi++)
#pragma unroll
        for (int ni = 0; ni < 4; ni++)
#pragma unroll
            for (int j = 0; j < 4; j++) acc[mi][ni][j] = 0.0f;

#define G1LD(KC, NB)                                                          \
    {                                                                         \
        int _k0 = ks + (KC) * 32;                                             \
        _Pragma("unroll")                                                     \
        for (int pr = 0; pr < 2; pr++) {                                      \
            const bf16* sa = pr ? g_ajlo : g_ajhi;                            \
            _Pragma("unroll")                                                 \
            for (int p = 0; p < 2; p++) {                                     \
                int e = t + 256 * p;                                          \
                int row = e >> 2, gg = e & 3;                                 \
                cpa16(su + (uint32_t)((NB) * 20480 + pr * 10240 + row * 80 + gg * 16), \
                      sa + (size_t)(m0 + row) * Nn + _k0 + gg * 8);           \
            }                                                                 \
            const bf16* sb = pr ? g_cblo : g_cbhi;                            \
            int k = t >> 3, gg2 = t & 7;                                      \
            cpa16(su + (uint32_t)(61440 + (NB) * 9216 + pr * 4608 + k * 144 + gg2 * 16), \
                  sb + (size_t)(_k0 + k) * NB1 + n0 + gg2 * 8);               \
        }                                                                     \
    }

    G1LD(0, 0);
    CP_COMMIT();
    G1LD(1, 1);
    CP_COMMIT();
    CP_WAIT1();
    __syncthreads();

    const int NIT = 32;
    for (int it = 0; it < NIT; it++) {
        int buf = it % 3;
        uint32_t aOff = (uint32_t)(buf * 20480);
        uint32_t bOff = (uint32_t)(buf * 9216);
#pragma unroll
        for (int s = 0; s < 2; s++) {
            uint32_t ah[2][4], al[2][4], bh[2][4], bl[2][4];
#pragma unroll
            for (int mi = 0; mi < 2; mi++) {
                LDSMX4(ah[mi], aB + aOff + mi * 1280 + s * 32);
                LDSMX4(al[mi], aB + aOff + 10240 + mi * 1280 + s * 32);
            }
#pragma unroll
            for (int nbk = 0; nbk < 2; nbk++) {
                LDSMX4T(bh[nbk], bB + bOff + s * 2304 + nbk * 32);
                LDSMX4T(bl[nbk], bB + bOff + 4608 + s * 2304 + nbk * 32);
            }
#pragma unroll
            for (int mi = 0; mi < 2; mi++)
#pragma unroll
                for (int ni = 0; ni < 4; ni++) {
                    uint32_t* fh = &bh[ni >> 1][(ni & 1) * 2];
                    uint32_t* fl = &bl[ni >> 1][(ni & 1) * 2];
                    MMA(acc[mi][ni], ah[mi], fh);
                    MMA(acc[mi][ni], al[mi], fh);
                    MMA(acc[mi][ni], ah[mi], fl);
                }
        }
        if (it + 2 < NIT) {
            G1LD(it + 2, (it + 2) % 3);
            CP_COMMIT();
        }
        if (it + 1 < NIT) {
            if (it + 2 < NIT) { CP_WAIT1(); } else { CP_WAIT0(); }
            __syncthreads();
        }
    }

    float* dst = g_pg1 + (size_t)blockIdx.z * Mm * NB1;
#pragma unroll
    for (int mi = 0; mi < 2; mi++) {
        int r0 = m0 + mw * 32 + mi * 16 + (lane >> 2);
#pragma unroll
        for (int ni = 0; ni < 4; ni++) {
            int col = n0 + nw * 32 + ni * 8 + (lane & 3) * 2;
            *(float2*)&dst[(size_t)r0 * NB1 + col] = make_float2(acc[mi][ni][0], acc[mi][ni][1]);
            *(float2*)&dst[(size_t)(r0 + 8) * NB1 + col] = make_float2(acc[mi][ni][2], acc[mi][ni][3]);
        }
    }
#undef G1LD
}

// sum 4 k-splits -> cg bf16 hi/lo (8-wide); col 257 = 1.0
__global__ void k_cg_split8() {
    int idx = blockIdx.x * 256 + threadIdx.x;     // over Mm*36
    if (idx >= Mm * 36) return;
    int m = idx / 36, c0 = (idx - m * 36) * 8;
    float s[8];
    {
        float4 a0 = make_float4(0.f, 0.f, 0.f, 0.f), a1 = a0;
#pragma unroll
        for (int sp = 0; sp < 4; sp++) {
            const float* p = &g_pg1[(size_t)sp * Mm * NB1 + (size_t)m * NB1 + c0];
            float4 b0 = *(const float4*)p;
            float4 b1 = *(const float4*)(p + 4);
            a0.x += b0.x; a0.y += b0.y; a0.z += b0.z; a0.w += b0.w;
            a1.x += b1.x; a1.y += b1.y; a1.z += b1.z; a1.w += b1.w;
        }
        s[0] = a0.x; s[1] = a0.y; s[2] = a0.z; s[3] = a0.w;
        s[4] = a1.x; s[5] = a1.y; s[6] = a1.z; s[7] = a1.w;
    }
    bf16 hv[8], lv[8];
#pragma unroll
    for (int j = 0; j < 8; j++) {
        int c = c0 + j;
        float v = (c < INDIM) ? s[j] : (c == INDIM ? 1.0f : 0.0f);
        bsplit(v, hv[j], lv[j]);
    }
    size_t o = (size_t)m * KP + c0;
    *(ull*)&g_cghi[o] = *(ull*)hv;  *(ull*)&g_cghi[o + 4] = *(ull*)(hv + 4);
    *(ull*)&g_cglo[o] = *(ull*)lv;  *(ull*)&g_cglo[o + 4] = *(ull*)(lv + 4);
}

// ---------------------------------------------------------------------------
// Gate GEMM: A K-slice persistent, B double-buffered, 2 CTA/SM. (round-13)
// ---------------------------------------------------------------------------
__global__ __launch_bounds__(256, 2) void k_mma2(
    const bf16* __restrict__ Ahi, const bf16* __restrict__ Alo,
    const bf16* __restrict__ Whi, const bf16* __restrict__ Wlo,
    const float* __restrict__ q,
    float* __restrict__ out0, float* __restrict__ out1,
    int ngate, int dper) {
    extern __shared__ char sm[];
    __shared__ float qs[128][16];
    uint32_t su = (uint32_t)__cvta_generic_to_shared(sm);
    int t = threadIdx.x, lane = t & 31, wid = t >> 5;
    int n0 = blockIdx.x * 64, m0 = blockIdx.y * 128;
    int gate = blockIdx.z % ngate;
    int rest = blockIdx.z / ngate;
    int kspl = rest & 1, dspl = rest >> 1;
    int d0 = dspl * dper;
    int kc0 = kspl ? 5 : 0, nkc = kspl ? 4 : 5;

    for (int e = t; e < 128 * dper; e += 256)
        qs[e / dper][e % dper] = q[(size_t)(m0 + e / dper) * QDIM + d0 + e % dper];

    int mw = wid >> 1, nw = wid & 1;
    uint32_t aB = su + (uint32_t)((mw * 32 + (lane & 15)) * 336 + (lane >> 4) * 16);
    uint32_t bB = su + 86016u + (uint32_t)((lane & 15) * 144 + (nw * 32 + (lane >> 4) * 8) * 2);

    int gr = nkc * 4;
#pragma unroll
    for (int pr = 0; pr < 2; pr++) {
        const bf16* sa = pr ? Alo : Ahi;
        for (int g = t; g < 128 * gr; g += 256) {
            int row = g / gr, gg = g - row * gr;
            cpa16(su + (uint32_t)(pr * 43008 + row * 336 + gg * 16),
                  sa + (size_t)(m0 + row) * KP + kc0 * 32 + gg * 8);
        }
    }

#define LDB2(DJ, KC, NB)                                                      \
    {                                                                         \
        int _d = d0 + (DJ);                                                   \
        size_t _wb = (((size_t)gate * 32 + _d) * KP + (kc0 + (KC)) * 32) * IS; \
        int k = t >> 3, gg = t & 7;                                           \
        cpa16(su + (uint32_t)(86016 + (NB) * 9216 + k * 144 + gg * 16),       \
              Whi + _wb + (size_t)k * IS + n0 + gg * 8);                      \
        cpa16(su + (uint32_t)(86016 + (NB) * 9216 + 4608 + k * 144 + gg * 16), \
              Wlo + _wb + (size_t)k * IS + n0 + gg * 8);                      \
    }

    LDB2(0, 0, 0);
    CP_COMMIT();
    CP_WAIT0();
    __syncthreads();

    float acc[2][4][4], c[2][4][4];
#pragma unroll
    for (int mi = 0; mi < 2; mi++)
#pragma unroll
        for (int ni = 0; ni < 4; ni++)
#pragma unroll
            for (int j = 0; j < 4; j++) acc[mi][ni][j] = 0.0f;

    const int J = dper * nkc;
    for (int j = 0; j < J; j++) {
        int dj = j / nkc, kc = j - dj * nkc;
        int buf = j & 1, nb = buf ^ 1;
        if (kc == 0) {
#pragma unroll
            for (int mi = 0; mi < 2; mi++)
#pragma unroll
                for (int ni = 0; ni < 4; ni++)
#pragma unroll
                    for (int jj = 0; jj < 4; jj++) c[mi][ni][jj] = 0.0f;
        }
        if (j + 1 < J) {
            int j2 = j + 1, dj2 = j2 / nkc, kc2 = j2 - dj2 * nkc;
            LDB2(dj2, kc2, nb);
            CP_COMMIT();
        }
#pragma unroll
        for (int s = 0; s < 2; s++) {
            uint32_t ah[2][4], al[2][4], bh[2][4], bl[2][4];
#pragma unroll
            for (int mi = 0; mi < 2; mi++) {
                LDSMX4(ah[mi], aB + mi * 5376 + kc * 64 + s * 32);
                LDSMX4(al[mi], aB + 43008 + mi * 5376 + kc * 64 + s * 32);
            }
#pragma unroll
            for (int nbk = 0; nbk < 2; nbk++) {
                LDSMX4T(bh[nbk], bB + buf * 9216 + s * 2304 + nbk * 32);
                LDSMX4T(bl[nbk], bB + buf * 9216 + 4608 + s * 2304 + nbk * 32);
            }
#pragma unroll
            for (int mi = 0; mi < 2; mi++)
#pragma unroll
                for (int ni = 0; ni < 4; ni++) {
                    uint32_t* fh = &bh[ni >> 1][(ni & 1) * 2];
                    uint32_t* fl = &bl[ni >> 1][(ni & 1) * 2];
                    MMA(c[mi][ni], ah[mi], fh);
                    MMA(c[mi][ni], al[mi], fh);
                    MMA(c[mi][ni], ah[mi], fl);
                }
        }
        if (kc == nkc - 1) {
#pragma unroll
            for (int mi = 0; mi < 2; mi++) {
                float q0 = qs[mw * 32 + mi * 16 + (lane >> 2)][dj];
                float q1 = qs[mw * 32 + mi * 16 + 8 + (lane >> 2)][dj];
#pragma unroll
                for (int ni = 0; ni < 4; ni++) {
                    acc[mi][ni][0] = fmaf(q0, c[mi][ni][0], acc[mi][ni][0]);
                    acc[mi][ni][1] = fmaf(q0, c[mi][ni][1], acc[mi][ni][1]);
                    acc[mi][ni][2] = fmaf(q1, c[mi][ni][2], acc[mi][ni][2]);
                    acc[mi][ni][3] = fmaf(q1, c[mi][ni][3], acc[mi][ni][3]);
                }
            }
        }
        CP_WAIT0();
        __syncthreads();
    }

    float* outp = (gate ? out1 : out0) + (size_t)rest * Mm * IS;
#pragma unroll
    for (int mi = 0; mi < 2; mi++) {
        int r0 = m0 + mw * 32 + mi * 16 + (lane >> 2);
#pragma unroll
        for (int ni = 0; ni < 4; ni++) {
            int col = n0 + nw * 32 + ni * 8 + (lane & 3) * 2;
            *(float2*)&outp[(size_t)r0 * IS + col] = make_float2(acc[mi][ni][0], acc[mi][ni][1]);
            *(float2*)&outp[(size_t)(r0 + 8) * IS + col] = make_float2(acc[mi][ni][2], acc[mi][ni][3]);
        }
    }
#undef LDB2
}

// reduce r,u (4 partials) + sigmoid
__global__ void k_gates_reduce() {
    int idx = blockIdx.x * 256 + threadIdx.x;
    if (idx >= Mm * IS / 4) return;
    const float4* pr = (const float4*)g_pr;
    const float4* pu = (const float4*)g_pu;
    float4 r = make_float4(0.f, 0.f, 0.f, 0.f);
    float4 u = make_float4(0.f, 0.f, 0.f, 0.f);
#pragma unroll
    for (int s = 0; s < 4; s++) {
        float4 a = pr[idx + (size_t)s * (Mm * IS / 4)];
        float4 b = pu[idx + (size_t)s * (Mm * IS / 4)];
        r.x += a.x; r.y += a.y; r.z += a.z; r.w += a.w;
        u.x += b.x; u.y += b.y; u.z += b.z; u.w += b.w;
    }
    r.x = sigmoidf_(r.x); r.y = sigmoidf_(r.y); r.z = sigmoidf_(r.z); r.w = sigmoidf_(r.w);
    u.x = sigmoidf_(u.x); u.y = sigmoidf_(u.y); u.z = sigmoidf_(u.z); u.w = sigmoidf_(u.w);
    ((float4*)g_r)[idx] = r;
    ((float4*)g_u)[idx] = u;
}

// cn -> bf16 hi/lo (8-wide); col 257 = 1.0
__global__ void k_pack_cn8(const float* __restrict__ x, const float* __restrict__ h,
                           const int* __restrict__ nodes) {
    int idx = blockIdx.x * 256 + threadIdx.x;     // over Mm*36
    if (idx >= Mm * 36) return;
    int m = idx / 36, c0 = (idx - m * 36) * 8;
    int nm = nodes[m];
    bf16 hv[8], lv[8];
#pragma unroll
    for (int j = 0; j < 8; j++) {
        int c = c0 + j;
        float v = 0.0f;
        if (c < XC) {
            v = x[(size_t)nm * XC + c];
        } else if (c < INDIM) {
            int jj = c - XC;
            v = g_r[(size_t)m * IS + jj] * h[(size_t)nm * IS + jj];
        } else if (c == INDIM) v = 1.0f;
        bsplit(v, hv[j], lv[j]);
    }
    size_t o = (size_t)m * KP + c0;
    *(ull*)&g_cnhi[o] = *(ull*)hv;  *(ull*)&g_cnhi[o + 4] = *(ull*)(hv + 4);
    *(ull*)&g_cnlo[o] = *(ull*)lv;  *(ull*)&g_cnlo[o + 4] = *(ull*)(lv + 4);
}

// reduce candidate (8 partials) + tanh + combine
__global__ void k_final_reduce(const float* __restrict__ h,
                               const int* __restrict__ nodes,
                               float* __restrict__ out) {
    int idx = blockIdx.x * 256 + threadIdx.x;
    if (idx >= Mm * IS / 4) return;
    int m  = idx / (IS / 4);
    int c4 = idx - m * (IS / 4);
    int nm = nodes[m];
    const float4* pc = (const float4*)g_pc;
    float4 c = make_float4(0.f, 0.f, 0.f, 0.f);
#pragma unroll
    for (int s = 0; s < 8; s++) {
        float4 a = pc[idx + (size_t)s * (Mm * IS / 4)];
        c.x += a.x; c.y += a.y; c.z += a.z; c.w += a.w;
    }
    float4 rr = ((const float4*)g_r)[idx];
    float4 uu = ((const float4*)g_u)[idx];
    float4 hv = *(const float4*)&h[(size_t)nm * IS + c4 * 4];
    float4 o;
    o.x = (1.0f - uu.x) * rr.x * hv.x + uu.x * tanhf(c.x);
    o.y = (1.0f - uu.y) * rr.y * hv.y + uu.y * tanhf(c.y);
    o.z = (1.0f - uu.z) * rr.z * hv.z + uu.z * tanhf(c.z);
    o.w = (1.0f - uu.w) * rr.w * hv.w + uu.w * tanhf(c.w);
    *(float4*)&out[(size_t)m * IS + c4 * 4] = o;
}

// ---------------------------------------------------------------------------
extern "C" void kernel_launch(void* const* d_in, const int* in_sizes, int n_in,
                              void* d_out, int out_size) {
    const float* x    = (const float*)d_in[0];
    const float* h    = (const float*)d_in[1];
    const float* q    = (const float*)d_in[2];
    const float* adj  = (const float*)d_in[3];
    const int*   nodes= (const int*)  d_in[4];
    const float* Wu   = (const float*)d_in[5];
    const float* bu   = (const float*)d_in[6];
    const float* Wr   = (const float*)d_in[7];
    const float* br   = (const float*)d_in[8];
    const float* Wc   = (const float*)d_in[9];
    const float* bc   = (const float*)d_in[10];
    float* out = (float*)d_out;

    static bool init = false;
    if (!init) {
        cudaFuncSetAttribute(k_mma_g1, cudaFuncAttributeMaxDynamicSharedMemorySize, 89088);
        cudaFuncSetAttribute(k_mma2, cudaFuncAttributeMaxDynamicSharedMemorySize, 104448);
        init = true;
    }

    bf16 *whi_p, *wlo_p, *cghi_p, *cglo_p, *cnhi_p, *cnlo_p;
    cudaGetSymbolAddress((void**)&whi_p, g_Whi);
    cudaGetSymbolAddress((void**)&wlo_p, g_Wlo);
    cudaGetSymbolAddress((void**)&cghi_p, g_cghi);
    cudaGetSymbolAddress((void**)&cglo_p, g_cglo);
    cudaGetSymbolAddress((void**)&cnhi_p, g_cnhi);
    cudaGetSymbolAddress((void**)&cnlo_p, g_cnlo);
    float *pr_p, *pu_p, *pc_p;
    cudaGetSymbolAddress((void**)&pr_p, g_pr);
    cudaGetSymbolAddress((void**)&pu_p, g_pu);
    cudaGetSymbolAddress((void**)&pc_p, g_pc);

    k_prep<<<PREP_CAT_BLKS + PREP_ADJ_BLKS + PREP_W_BLKS, 256>>>(
        x, h, adj, nodes, Wr, Wu, Wc, br, bu, bc);
    k_mma_g1<<<dim3(5, 16, 4), 256, 89088>>>();
    k_cg_split8<<<(Mm * 36 + 255) / 256, 256>>>();
    // gates r+u: z = gate(2) x (kspl(2) x dspl(2)), dper=16 -> 256 CTAs
    k_mma2<<<dim3(2, 16, 8), 256, 104448>>>(cghi_p, cglo_p, whi_p, wlo_p, q, pr_p, pu_p, 2, 16);
    k_gates_reduce<<<(Mm * IS / 4 + 255) / 256, 256>>>();
    k_pack_cn8<<<(Mm * 36 + 255) / 256, 256>>>(x, h, nodes);
    // candidate: z = kspl(2) x dspl(4), dper=8 -> 256 CTAs
    k_mma2<<<dim3(2, 16, 8), 256, 104448>>>(cnhi_p, cnlo_p,
                                            whi_p + (size_t)2 * 32 * KP * IS,
                                            wlo_p + (size_t)2 * 32 * KP * IS,
                                            q, pc_p, pc_p, 1, 8);
    k_final_reduce<<<(Mm * IS / 4 + 255) / 256, 256>>>(h, nodes, out);
}

// round 15
// speedup vs baseline: 1.1708x; 1.0001x over previous
#include <cuda_runtime.h>
#include <cuda_bf16.h>
#include <math.h>
#include <stdint.h>

#define Nn   4096
#define Mm   2048
#define IS   128
#define XC   129
#define INDIM 257
#define QDIM 32
#define KP   288      // gate-GEMM K (257 + bias col + pad)
#define NB1  320      // pg1 row stride

typedef unsigned long long ull;
typedef __nv_bfloat16 bf16;

// Scratch
__device__ __align__(16) bf16 g_cbhi[Nn * NB1];
__device__ __align__(16) bf16 g_cblo[Nn * NB1];
__device__ __align__(16) bf16 g_ajhi[Mm * Nn];
__device__ __align__(16) bf16 g_ajlo[Mm * Nn];
__device__ float g_pg1 [4 * Mm * NB1];
__device__ float g_c256[Mm];
__device__ __align__(16) bf16 g_cghi[Mm * KP];
__device__ __align__(16) bf16 g_cglo[Mm * KP];
__device__ __align__(16) bf16 g_cnhi[Mm * KP];
__device__ __align__(16) bf16 g_cnlo[Mm * KP];
__device__ __align__(16) bf16 g_Whi[(size_t)3 * 32 * KP * IS];
__device__ __align__(16) bf16 g_Wlo[(size_t)3 * 32 * KP * IS];
__device__ float g_pr [4 * Mm * IS];
__device__ float g_pu [4 * Mm * IS];
__device__ float g_pc [8 * Mm * IS];
__device__ float g_r  [Mm * IS];
__device__ float g_u  [Mm * IS];

__device__ __forceinline__ float sigmoidf_(float v) { return 1.0f / (1.0f + expf(-v)); }
__device__ __forceinline__ void cpa16(uint32_t dst, const void* src) {
    asm volatile("cp.async.ca.shared.global [%0], [%1], 16;" :: "r"(dst), "l"(src));
}
#define CP_COMMIT() asm volatile("cp.async.commit_group;")
#define CP_WAIT0()  asm volatile("cp.async.wait_group 0;")
#define CP_WAIT1()  asm volatile("cp.async.wait_group 1;")

#define LDSMX4(R, ADDR)                                                       \
    asm volatile("ldmatrix.sync.aligned.m8n8.x4.shared.b16 {%0,%1,%2,%3}, [%4];" \
        : "=r"((R)[0]), "=r"((R)[1]), "=r"((R)[2]), "=r"((R)[3]) : "r"(ADDR))
#define LDSMX4T(R, ADDR)                                                      \
    asm volatile("ldmatrix.sync.aligned.m8n8.x4.trans.shared.b16 {%0,%1,%2,%3}, [%4];" \
        : "=r"((R)[0]), "=r"((R)[1]), "=r"((R)[2]), "=r"((R)[3]) : "r"(ADDR))
#define MMA(C, A, B)                                                          \
    asm volatile("mma.sync.aligned.m16n8k16.row.col.f32.bf16.bf16.f32 "       \
        "{%0,%1,%2,%3}, {%4,%5,%6,%7}, {%8,%9}, {%0,%1,%2,%3};"               \
        : "+f"((C)[0]), "+f"((C)[1]), "+f"((C)[2]), "+f"((C)[3])              \
        : "r"((A)[0]), "r"((A)[1]), "r"((A)[2]), "r"((A)[3]),                 \
          "r"((B)[0]), "r"((B)[1]))

__device__ __forceinline__ void bsplit(float v, bf16& hi, bf16& lo) {
    hi = __float2bfloat16(v);
    lo = __float2bfloat16(v - __bfloat162float(hi));
}

// ---------------------------------------------------------------------------
// Fused prep: cat-split | adj-split | W-split. 16B stores throughout.
// ---------------------------------------------------------------------------
#define PREP_CAT_BLKS 640     // Nn*40 / 256
#define PREP_ADJ_BLKS 8192    // Mm*Nn/4 / 256
#define PREP_W_BLKS   1728    // 3*32*288*16 / 256

__global__ void k_prep(const float* __restrict__ x, const float* __restrict__ h,
                       const float* __restrict__ adj, const int* __restrict__ nodes,
                       const float* __restrict__ Wr, const float* __restrict__ Wu,
                       const float* __restrict__ Wc, const float* __restrict__ br,
                       const float* __restrict__ bu, const float* __restrict__ bc) {
    int b = blockIdx.x, t = threadIdx.x;
    if (b < PREP_CAT_BLKS) {
        int idx = b * 256 + t;
        int row = idx / 40, c0 = (idx - row * 40) * 8;
        bf16 hv[8], lv[8];
#pragma unroll
        for (int j = 0; j < 8; j++) {
            int c = c0 + j;
            float v = 0.0f;
            if (c < XC)        v = x[row * XC + c];
            else if (c < INDIM) v = h[row * IS + (c - XC)];
            bsplit(v, hv[j], lv[j]);
        }
        size_t o = (size_t)row * NB1 + c0;
        *(ull*)&g_cbhi[o] = *(ull*)hv;  *(ull*)&g_cbhi[o + 4] = *(ull*)(hv + 4);
        *(ull*)&g_cblo[o] = *(ull*)lv;  *(ull*)&g_cblo[o + 4] = *(ull*)(lv + 4);
    } else if (b < PREP_CAT_BLKS + PREP_ADJ_BLKS) {
        int i4 = (b - PREP_CAT_BLKS) * 256 + t;
        int m = i4 >> 10;
        int k4 = (i4 & 1023) * 4;
        float4 v = *(const float4*)&adj[(size_t)nodes[m] * Nn + k4];
        bf16 hh[4], ll[4];
        bsplit(v.x, hh[0], ll[0]); bsplit(v.y, hh[1], ll[1]);
        bsplit(v.z, hh[2], ll[2]); bsplit(v.w, hh[3], ll[3]);
        *(ull*)&g_ajhi[(size_t)m * Nn + k4] = *(ull*)hh;
        *(ull*)&g_ajlo[(size_t)m * Nn + k4] = *(ull*)ll;
    } else {
        int idx = (b - PREP_CAT_BLKS - PREP_ADJ_BLKS) * 256 + t;
        int n8 = idx & 15;
        int r = idx >> 4;
        int k = r % KP; r /= KP;
        int d = r % 32;
        int g = r / 32;
        const float* W = (g == 0) ? Wr : (g == 1) ? Wu : Wc;
        const float* bb = (g == 0) ? br : (g == 1) ? bu : bc;
        bf16 hv[8], lv[8];
        if (k < INDIM) {
            const float* src = &W[((size_t)d * INDIM + k) * IS + n8 * 8];
            float4 a0 = *(const float4*)src;
            float4 a1 = *(const float4*)(src + 4);
            bsplit(a0.x, hv[0], lv[0]); bsplit(a0.y, hv[1], lv[1]);
            bsplit(a0.z, hv[2], lv[2]); bsplit(a0.w, hv[3], lv[3]);
            bsplit(a1.x, hv[4], lv[4]); bsplit(a1.y, hv[5], lv[5]);
            bsplit(a1.z, hv[6], lv[6]); bsplit(a1.w, hv[7], lv[7]);
        } else if (k == INDIM) {
            const float* src = &bb[d * IS + n8 * 8];
            float4 a0 = *(const float4*)src;
            float4 a1 = *(const float4*)(src + 4);
            bsplit(a0.x, hv[0], lv[0]); bsplit(a0.y, hv[1], lv[1]);
            bsplit(a0.z, hv[2], lv[2]); bsplit(a0.w, hv[3], lv[3]);
            bsplit(a1.x, hv[4], lv[4]); bsplit(a1.y, hv[5], lv[5]);
            bsplit(a1.z, hv[6], lv[6]); bsplit(a1.w, hv[7], lv[7]);
        } else {
#pragma unroll
            for (int j = 0; j < 8; j++) { hv[j] = __float2bfloat16(0.f); lv[j] = hv[j]; }
        }
        size_t o = ((size_t)(g * 32 + d) * KP + k) * IS + n8 * 8;
        *(ull*)&g_Whi[o] = *(ull*)hv;  *(ull*)&g_Whi[o + 4] = *(ull*)(hv + 4);
        *(ull*)&g_Wlo[o] = *(ull*)lv;  *(ull*)&g_Wlo[o + 4] = *(ull*)(lv + 4);
    }
}

// ---------------------------------------------------------------------------
// Column 256 of cg: fp32 matvec  c256[m] = adj[nodes[m],:] . h[:,127]
// grid 256 blocks x 256 thr; warp per row.
// ---------------------------------------------------------------------------
__global__ void k_c256(const float* __restrict__ adj, const int* __restrict__ nodes,
                       const float* __restrict__ h) {
    __shared__ float sh[4096];
    int t = threadIdx.x, wid = t >> 5, lane = t & 31;
    for (int k = t; k < Nn; k += 256) sh[k] = h[(size_t)k * IS + 127];
    __syncthreads();
    int m = blockIdx.x * 8 + wid;
    const float* ar = adj + (size_t)nodes[m] * Nn;
    float s = 0.0f;
#pragma unroll 16
    for (int i = 0; i < 128; i++) {
        int k = lane + 32 * i;
        s += ar[k] * sh[k];
    }
#pragma unroll
    for (int o = 16; o; o >>= 1) s += __shfl_xor_sync(0xffffffffu, s, o);
    if (lane == 0) g_c256[m] = s;
}

// ---------------------------------------------------------------------------
// Tensor GEMM1: BM=128, BN=64, cols 0-255 only. grid (4, 16, 4) = 256 CTAs,
// single wave at 2 CTA/SM. 3-stage pipeline. dyn smem 89088.
// ---------------------------------------------------------------------------
__global__ __launch_bounds__(256, 2) void k_mma_g1() {
    extern __shared__ char sm[];
    uint32_t su = (uint32_t)__cvta_generic_to_shared(sm);
    int t = threadIdx.x, lane = t & 31, wid = t >> 5;
    int n0 = blockIdx.x * 64, m0 = blockIdx.y * 128, ks = blockIdx.z * 1024;
    int mw = wid >> 1, nw = wid & 1;
    uint32_t aB = su + (uint32_t)((mw * 32 + (lane & 15)) * 80 + (lane >> 4) * 16);
    uint32_t bB = su + 61440u + (uint32_t)((lane & 15) * 144 + (nw * 32 + (lane >> 4) * 8) * 2);

    float acc[2][4][4];
#pragma unroll
    for (int mi = 0; mi < 2; mi++)
#pragma unroll
        for (int ni = 0; ni < 4; ni++)
#pragma unroll
            for (int j = 0; j < 4; j++) acc[mi][ni][j] = 0.0f;

#define G1LD(KC, NB)                                                          \
    {                                                                         \
        int _k0 = ks + (KC) * 32;                                             \
        _Pragma("unroll")                                                     \
        for (int pr = 0; pr < 2; pr++) {                                      \
            const bf16* sa = pr ? g_ajlo : g_ajhi;                            \
            _Pragma("unroll")                                                 \
            for (int p = 0; p < 2; p++) {                                     \
                int e = t + 256 * p;                                          \
                int row = e >> 2, gg = e & 3;                                 \
                cpa16(su + (uint32_t)((NB) * 20480 + pr * 10240 + row * 80 + gg * 16), \
                      sa + (size_t)(m0 + row) * Nn + _k0 + gg * 8);           \
            }                                                                 \
            const bf16* sb = pr ? g_cblo : g_cbhi;                            \
            int k = t >> 3, gg2 = t & 7;                                      \
            cpa16(su + (uint32_t)(61440 + (NB) * 9216 + pr * 4608 + k * 144 + gg2 * 16), \
                  sb + (size_t)(_k0 + k) * NB1 + n0 + gg2 * 8);               \
        }                                                                     \
    }

    G1LD(0, 0);
    CP_COMMIT();
    G1LD(1, 1);
    CP_COMMIT();
    CP_WAIT1();
    __syncthreads();

    const int NIT = 32;
    for (int it = 0; it < NIT; it++) {
        int buf = it % 3;
        uint32_t aOff = (uint32_t)(buf * 20480);
        uint32_t bOff = (uint32_t)(buf * 9216);
#pragma unroll
        for (int s = 0; s < 2; s++) {
            uint32_t ah[2][4], al[2][4], bh[2][4], bl[2][4];
#pragma unroll
            for (int mi = 0; mi < 2; mi++) {
                LDSMX4(ah[mi], aB + aOff + mi * 1280 + s * 32);
                LDSMX4(al[mi], aB + aOff + 10240 + mi * 1280 + s * 32);
            }
#pragma unroll
            for (int nbk = 0; nbk < 2; nbk++) {
                LDSMX4T(bh[nbk], bB + bOff + s * 2304 + nbk * 32);
                LDSMX4T(bl[nbk], bB + bOff + 4608 + s * 2304 + nbk * 32);
            }
#pragma unroll
            for (int mi = 0; mi < 2; mi++)
#pragma unroll
                for (int ni = 0; ni < 4; ni++) {
                    uint32_t* fh = &bh[ni >> 1][(ni & 1) * 2];
                    uint32_t* fl = &bl[ni >> 1][(ni & 1) * 2];
                    MMA(acc[mi][ni], ah[mi], fh);
                    MMA(acc[mi][ni], al[mi], fh);
                    MMA(acc[mi][ni], ah[mi], fl);
                }
        }
        if (it + 2 < NIT) {
            G1LD(it + 2, (it + 2) % 3);
            CP_COMMIT();
        }
        if (it + 1 < NIT) {
            if (it + 2 < NIT) { CP_WAIT1(); } else { CP_WAIT0(); }
            __syncthreads();
        }
    }

    float* dst = g_pg1 + (size_t)blockIdx.z * Mm * NB1;
#pragma unroll
    for (int mi = 0; mi < 2; mi++) {
        int r0 = m0 + mw * 32 + mi * 16 + (lane >> 2);
#pragma unroll
        for (int ni = 0; ni < 4; ni++) {
            int col = n0 + nw * 32 + ni * 8 + (lane & 3) * 2;
            *(float2*)&dst[(size_t)r0 * NB1 + col] = make_float2(acc[mi][ni][0], acc[mi][ni][1]);
            *(float2*)&dst[(size_t)(r0 + 8) * NB1 + col] = make_float2(acc[mi][ni][2], acc[mi][ni][3]);
        }
    }
#undef G1LD
}

// sum 4 k-splits (cols<256) + c256 + bias-1 -> cg bf16 hi/lo (8-wide)
__global__ void k_cg_split8() {
    int idx = blockIdx.x * 256 + threadIdx.x;     // over Mm*36
    if (idx >= Mm * 36) return;
    int m = idx / 36, c0 = (idx - m * 36) * 8;
    bf16 hv[8], lv[8];
    if (c0 < 256) {
        float4 a0 = make_float4(0.f, 0.f, 0.f, 0.f), a1 = a0;
#pragma unroll
        for (int sp = 0; sp < 4; sp++) {
            const float* p = &g_pg1[(size_t)sp * Mm * NB1 + (size_t)m * NB1 + c0];
            float4 b0 = *(const float4*)p;
            float4 b1 = *(const float4*)(p + 4);
            a0.x += b0.x; a0.y += b0.y; a0.z += b0.z; a0.w += b0.w;
            a1.x += b1.x; a1.y += b1.y; a1.z += b1.z; a1.w += b1.w;
        }
        float s[8] = {a0.x, a0.y, a0.z, a0.w, a1.x, a1.y, a1.z, a1.w};
#pragma unroll
        for (int j = 0; j < 8; j++) bsplit(s[j], hv[j], lv[j]);
    } else {
#pragma unroll
        for (int j = 0; j < 8; j++) {
            int c = c0 + j;
            float v = (c == 256) ? g_c256[m] : (c == INDIM ? 1.0f : 0.0f);
            bsplit(v, hv[j], lv[j]);
        }
    }
    size_t o = (size_t)m * KP + c0;
    *(ull*)&g_cghi[o] = *(ull*)hv;  *(ull*)&g_cghi[o + 4] = *(ull*)(hv + 4);
    *(ull*)&g_cglo[o] = *(ull*)lv;  *(ull*)&g_cglo[o + 4] = *(ull*)(lv + 4);
}

// ---------------------------------------------------------------------------
// Gate GEMM: A K-slice persistent, B 3-stage pipeline with 16-K half-chunk
// stages (4608B x3). dyn smem 99840 (+8192 static qs) -> 2 CTA/SM.
// z = gate + ngate*(kspl + 2*dspl). kspl0: chunks 0-4, kspl1: 5-8.
// ---------------------------------------------------------------------------
__global__ __launch_bounds__(256, 2) void k_mma2(
    const bf16* __restrict__ Ahi, const bf16* __restrict__ Alo,
    const bf16* __restrict__ Whi, const bf16* __restrict__ Wlo,
    const float* __restrict__ q,
    float* __restrict__ out0, float* __restrict__ out1,
    int ngate, int dper) {
    extern __shared__ char sm[];
    __shared__ float qs[128][16];
    uint32_t su = (uint32_t)__cvta_generic_to_shared(sm);
    int t = threadIdx.x, lane = t & 31, wid = t >> 5;
    int n0 = blockIdx.x * 64, m0 = blockIdx.y * 128;
    int gate = blockIdx.z % ngate;
    int rest = blockIdx.z / ngate;
    int kspl = rest & 1, dspl = rest >> 1;
    int d0 = dspl * dper;
    int kc0 = kspl ? 5 : 0, nkc = kspl ? 4 : 5;
    int nkc2 = nkc * 2;

    for (int e = t; e < 128 * dper; e += 256)
        qs[e / dper][e % dper] = q[(size_t)(m0 + e / dper) * QDIM + d0 + e % dper];

    int mw = wid >> 1, nw = wid & 1;
    uint32_t aB = su + (uint32_t)((mw * 32 + (lane & 15)) * 336 + (lane >> 4) * 16);
    uint32_t bB = su + 86016u + (uint32_t)((lane & 15) * 144 + (nw * 32 + (lane >> 4) * 8) * 2);

    // load A K-slice once (hi+lo) as its own cp.async group
    int gr = nkc * 4;
#pragma unroll
    for (int pr = 0; pr < 2; pr++) {
        const bf16* sa = pr ? Alo : Ahi;
        for (int g = t; g < 128 * gr; g += 256) {
            int row = g / gr, gg = g - row * gr;
            cpa16(su + (uint32_t)(pr * 43008 + row * 336 + gg * 16),
                  sa + (size_t)(m0 + row) * KP + kc0 * 32 + gg * 8);
        }
    }
    CP_COMMIT();

    // stage loader: stage ST = (dj*nkc + kc)*2 + s ; 16 k-rows, hi+lo
#define LDBH(ST, NB)                                                          \
    {                                                                         \
        int _st = (ST);                                                       \
        int _dj = _st / nkc2;                                                 \
        int _rem = _st - _dj * nkc2;                                          \
        int _kc = _rem >> 1, _s = _rem & 1;                                   \
        size_t _wb = (((size_t)gate * 32 + d0 + _dj) * KP                      \
                      + (kc0 + _kc) * 32 + _s * 16) * IS;                     \
        int _pr = t >> 7;                                                     \
        int _row = (t & 127) >> 3, _gg = t & 7;                               \
        const bf16* _src = _pr ? Wlo : Whi;                                   \
        cpa16(su + (uint32_t)(86016 + (NB) * 4608 + _pr * 2304 + _row * 144 + _gg * 16), \
              _src + _wb + (size_t)_row * IS + n0 + _gg * 8);                 \
    }

    LDBH(0, 0);
    CP_COMMIT();
    LDBH(1, 1);
    CP_COMMIT();
    CP_WAIT1();      // A + stage0 complete
    __syncthreads();

    float acc[2][4][4], c[2][4][4];
#pragma unroll
    for (int mi = 0; mi < 2; mi++)
#pragma unroll
        for (int ni = 0; ni < 4; ni++)
#pragma unroll
            for (int j = 0; j < 4; j++) acc[mi][ni][j] = 0.0f;

    const int S = dper * nkc2;
    for (int st = 0; st < S; st++) {
        int dj = st / nkc2;
        int rem = st - dj * nkc2;
        int kc = rem >> 1, s = rem & 1;
        int buf = st % 3;
        uint32_t bOff = (uint32_t)(buf * 4608);
        if (rem == 0) {
#pragma unroll
            for (int mi = 0; mi < 2; mi++)
#pragma unroll
                for (int ni = 0; ni < 4; ni++)
#pragma unroll
                    for (int jj = 0; jj < 4; jj++) c[mi][ni][jj] = 0.0f;
        }
        {
            uint32_t ah[2][4], al[2][4], bh[2][4], bl[2][4];
#pragma unroll
            for (int mi = 0; mi < 2; mi++) {
                LDSMX4(ah[mi], aB + mi * 5376 + kc * 64 + s * 32);
                LDSMX4(al[mi], aB + 43008 + mi * 5376 + kc * 64 + s * 32);
            }
#pragma unroll
            for (int nbk = 0; nbk < 2; nbk++) {
                LDSMX4T(bh[nbk], bB + bOff + nbk * 32);
                LDSMX4T(bl[nbk], bB + bOff + 2304 + nbk * 32);
            }
#pragma unroll
            for (int mi = 0; mi < 2; mi++)
#pragma unroll
                for (int ni = 0; ni < 4; ni++) {
                    uint32_t* fh = &bh[ni >> 1][(ni & 1) * 2];
                    uint32_t* fl = &bl[ni >> 1][(ni & 1) * 2];
                    MMA(c[mi][ni], ah[mi], fh);
                    MMA(c[mi][ni], al[mi], fh);
                    MMA(c[mi][ni], ah[mi], fl);
                }
        }
        if (rem == nkc2 - 1) {
#pragma unroll
            for (int mi = 0; mi < 2; mi++) {
                float q0 = qs[mw * 32 + mi * 16 + (lane >> 2)][dj];
                float q1 = qs[mw * 32 + mi * 16 + 8 + (lane >> 2)][dj];
#pragma unroll
                for (int ni = 0; ni < 4; ni++) {
                    acc[mi][ni][0] = fmaf(q0, c[mi][ni][0], acc[mi][ni][0]);
                    acc[mi][ni][1] = fmaf(q0, c[mi][ni][1], acc[mi][ni][1]);
                    acc[mi][ni][2] = fmaf(q1, c[mi][ni][2], acc[mi][ni][2]);
                    acc[mi][ni][3] = fmaf(q1, c[mi][ni][3], acc[mi][ni][3]);
                }
            }
        }
        if (st + 2 < S) {
            LDBH(st + 2, (st + 2) % 3);
            CP_COMMIT();
        }
        if (st + 1 < S) {
            if (st + 2 < S) { CP_WAIT1(); } else { CP_WAIT0(); }
            __syncthreads();
        }
    }

    float* outp = (gate ? out1 : out0) + (size_t)rest * Mm * IS;
#pragma unroll
    for (int mi = 0; mi < 2; mi++) {
        int r0 = m0 + mw * 32 + mi * 16 + (lane >> 2);
#pragma unroll
        for (int ni = 0; ni < 4; ni++) {
            int col = n0 + nw * 32 + ni * 8 + (lane & 3) * 2;
            *(float2*)&outp[(size_t)r0 * IS + col] = make_float2(acc[mi][ni][0], acc[mi][ni][1]);
            *(float2*)&outp[(size_t)(r0 + 8) * IS + col] = make_float2(acc[mi][ni][2], acc[mi][ni][3]);
        }
    }
#undef LDBH
}

// reduce r,u (4 partials) + sigmoid
__global__ void k_gates_reduce() {
    int idx = blockIdx.x * 256 + threadIdx.x;
    if (idx >= Mm * IS / 4) return;
    const float4* pr = (const float4*)g_pr;
    const float4* pu = (const float4*)g_pu;
    float4 r = make_float4(0.f, 0.f, 0.f, 0.f);
    float4 u = make_float4(0.f, 0.f, 0.f, 0.f);
#pragma unroll
    for (int s = 0; s < 4; s++) {
        float4 a = pr[idx + (size_t)s * (Mm * IS / 4)];
        float4 b = pu[idx + (size_t)s * (Mm * IS / 4)];
        r.x += a.x; r.y += a.y; r.z += a.z; r.w += a.w;
        u.x += b.x; u.y += b.y; u.z += b.z; u.w += b.w;
    }
    r.x = sigmoidf_(r.x); r.y = sigmoidf_(r.y); r.z = sigmoidf_(r.z); r.w = sigmoidf_(r.w);
    u.x = sigmoidf_(u.x); u.y = sigmoidf_(u.y); u.z = sigmoidf_(u.z); u.w = sigmoidf_(u.w);
    ((float4*)g_r)[idx] = r;
    ((float4*)g_u)[idx] = u;
}

// cn -> bf16 hi/lo (8-wide); col 257 = 1.0
__global__ void k_pack_cn8(const float* __restrict__ x, const float* __restrict__ h,
                           const int* __restrict__ nodes) {
    int idx = blockIdx.x * 256 + threadIdx.x;     // over Mm*36
    if (idx >= Mm * 36) return;
    int m = idx / 36, c0 = (idx - m * 36) * 8;
    int nm = nodes[m];
    bf16 hv[8], lv[8];
#pragma unroll
    for (int j = 0; j < 8; j++) {
        int c = c0 + j;
        float v = 0.0f;
        if (c < XC) {
            v = x[(size_t)nm * XC + c];
        } else if (c < INDIM) {
            int jj = c - XC;
            v = g_r[(size_t)m * IS + jj] * h[(size_t)nm * IS + jj];
        } else if (c == INDIM) v = 1.0f;
        bsplit(v, hv[j], lv[j]);
    }
    size_t o = (size_t)m * KP + c0;
    *(ull*)&g_cnhi[o] = *(ull*)hv;  *(ull*)&g_cnhi[o + 4] = *(ull*)(hv + 4);
    *(ull*)&g_cnlo[o] = *(ull*)lv;  *(ull*)&g_cnlo[o + 4] = *(ull*)(lv + 4);
}

// reduce candidate (8 partials) + tanh + combine
__global__ void k_final_reduce(const float* __restrict__ h,
                               const int* __restrict__ nodes,
                               float* __restrict__ out) {
    int idx = blockIdx.x * 256 + threadIdx.x;
    if (idx >= Mm * IS / 4) return;
    int m  = idx / (IS / 4);
    int c4 = idx - m * (IS / 4);
    int nm = nodes[m];
    const float4* pc = (const float4*)g_pc;
    float4 c = make_float4(0.f, 0.f, 0.f, 0.f);
#pragma unroll
    for (int s = 0; s < 8; s++) {
        float4 a = pc[idx + (size_t)s * (Mm * IS / 4)];
        c.x += a.x; c.y += a.y; c.z += a.z; c.w += a.w;
    }
    float4 rr = ((const float4*)g_r)[idx];
    float4 uu = ((const float4*)g_u)[idx];
    float4 hv = *(const float4*)&h[(size_t)nm * IS + c4 * 4];
    float4 o;
    o.x = (1.0f - uu.x) * rr.x * hv.x + uu.x * tanhf(c.x);
    o.y = (1.0f - uu.y) * rr.y * hv.y + uu.y * tanhf(c.y);
    o.z = (1.0f - uu.z) * rr.z * hv.z + uu.z * tanhf(c.z);
    o.w = (1.0f - uu.w) * rr.w * hv.w + uu.w * tanhf(c.w);
    *(float4*)&out[(size_t)m * IS + c4 * 4] = o;
}

// ---------------------------------------------------------------------------
extern "C" void kernel_launch(void* const* d_in, const int* in_sizes, int n_in,
                              void* d_out, int out_size) {
    const float* x    = (const float*)d_in[0];
    const float* h    = (const float*)d_in[1];
    const float* q    = (const float*)d_in[2];
    const float* adj  = (const float*)d_in[3];
    const int*   nodes= (const int*)  d_in[4];
    const float* Wu   = (const float*)d_in[5];
    const float* bu   = (const float*)d_in[6];
    const float* Wr   = (const float*)d_in[7];
    const float* br   = (const float*)d_in[8];
    const float* Wc   = (const float*)d_in[9];
    const float* bc   = (const float*)d_in[10];
    float* out = (float*)d_out;

    static bool init = false;
    if (!init) {
        cudaFuncSetAttribute(k_mma_g1, cudaFuncAttributeMaxDynamicSharedMemorySize, 89088);
        cudaFuncSetAttribute(k_mma2, cudaFuncAttributeMaxDynamicSharedMemorySize, 99840);
        init = true;
    }

    bf16 *whi_p, *wlo_p, *cghi_p, *cglo_p, *cnhi_p, *cnlo_p;
    cudaGetSymbolAddress((void**)&whi_p, g_Whi);
    cudaGetSymbolAddress((void**)&wlo_p, g_Wlo);
    cudaGetSymbolAddress((void**)&cghi_p, g_cghi);
    cudaGetSymbolAddress((void**)&cglo_p, g_cglo);
    cudaGetSymbolAddress((void**)&cnhi_p, g_cnhi);
    cudaGetSymbolAddress((void**)&cnlo_p, g_cnlo);
    float *pr_p, *pu_p, *pc_p;
    cudaGetSymbolAddress((void**)&pr_p, g_pr);
    cudaGetSymbolAddress((void**)&pu_p, g_pu);
    cudaGetSymbolAddress((void**)&pc_p, g_pc);

    k_prep<<<PREP_CAT_BLKS + PREP_ADJ_BLKS + PREP_W_BLKS, 256>>>(
        x, h, adj, nodes, Wr, Wu, Wc, br, bu, bc);
    k_c256<<<Mm / 8, 256>>>(adj, nodes, h);
    k_mma_g1<<<dim3(4, 16, 4), 256, 89088>>>();
    k_cg_split8<<<(Mm * 36 + 255) / 256, 256>>>();
    // gates r+u: z = gate(2) x (kspl(2) x dspl(2)), dper=16 -> 256 CTAs
    k_mma2<<<dim3(2, 16, 8), 256, 99840>>>(cghi_p, cglo_p, whi_p, wlo_p, q, pr_p, pu_p, 2, 16);
    k_gates_reduce<<<(Mm * IS / 4 + 255) / 256, 256>>>();
    k_pack_cn8<<<(Mm * 36 + 255) / 256, 256>>>(x, h, nodes);
    // candidate: z = kspl(2) x dspl(4), dper=8 -> 256 CTAs
    k_mma2<<<dim3(2, 16, 8), 256, 99840>>>(cnhi_p, cnlo_p,
                                           whi_p + (size_t)2 * 32 * KP * IS,
                                           wlo_p + (size_t)2 * 32 * KP * IS,
                                           q, pc_p, pc_p, 1, 8);
    k_final_reduce<<<(Mm * IS / 4 + 255) / 256, 256>>>(h, nodes, out);
}